// round 1
// baseline (speedup 1.0000x reference)
#include <cuda_runtime.h>
#include <cuda_bf16.h>
#include <math.h>

// Problem constants
#define cB   8
#define cS   512
#define cH   768
#define cL   12
#define cNH  12
#define cDH  64
#define cDFF 3072
#define cNL  19
#define cM   (cB * cS)   // 4096 rows

// ---------------------------------------------------------------------------
// Scratch (static device globals; no allocations anywhere)
// ---------------------------------------------------------------------------
__device__ float g_x   [cM * cH];
__device__ float g_tmp [cM * cH];
__device__ float g_q   [cM * cH];
__device__ float g_k   [cM * cH];
__device__ float g_v   [cM * cH];
__device__ float g_ctx [cM * cH];
__device__ float g_ffn [cM * cDFF];
__device__ float g_scores[(size_t)cB * cNH * cS * cS];
__device__ float g_logits[cM * cNL];
__device__ float g_pb  [cB];

// ---------------------------------------------------------------------------
// GELU (tanh approximation, matching jax.nn.gelu default)
// ---------------------------------------------------------------------------
__device__ __forceinline__ float gelu_tanh(float x) {
    float c = 0.7978845608028654f * (x + 0.044715f * x * x * x);
    return 0.5f * x * (1.0f + tanhf(c));
}

// ---------------------------------------------------------------------------
// Generic SGEMM: C[M,N] = A[M,K] @ B[K,N] + bias, optional GELU / residual.
// 128x128 tile, BK=8, 256 threads, 8x8 micro-tile. M%128==0, N%128==0, K%8==0.
// EPI: 0 = bias, 1 = bias+gelu, 2 = bias+residual
// ---------------------------------------------------------------------------
template <int EPI>
__global__ __launch_bounds__(256)
void sgemm_k(const float* __restrict__ A, const float* __restrict__ Bm,
             const float* __restrict__ bias, const float* __restrict__ resid,
             float* __restrict__ C, int M, int N, int K)
{
    __shared__ float As[8][128];
    __shared__ float Bs[8][128];

    const int tid = threadIdx.x;
    const int rowBase = blockIdx.y * 128;
    const int colBase = blockIdx.x * 128;
    const int tr = tid >> 4;        // 0..15
    const int tc = tid & 15;        // 0..15

    float acc[8][8];
    #pragma unroll
    for (int i = 0; i < 8; i++)
        #pragma unroll
        for (int j = 0; j < 8; j++) acc[i][j] = 0.0f;

    const int aRow = tid >> 1;            // 0..127
    const int aK   = (tid & 1) * 4;       // 0 or 4
    const int bK   = tid >> 5;            // 0..7
    const int bN   = (tid & 31) * 4;      // 0..124

    const float* Aptr = A + (size_t)(rowBase + aRow) * K + aK;
    const float* Bptr = Bm + (size_t)bK * N + colBase + bN;

    for (int k0 = 0; k0 < K; k0 += 8) {
        float4 av = *(const float4*)(Aptr + k0);
        float4 bv = *(const float4*)(Bptr + (size_t)k0 * N);
        As[aK + 0][aRow] = av.x;
        As[aK + 1][aRow] = av.y;
        As[aK + 2][aRow] = av.z;
        As[aK + 3][aRow] = av.w;
        *(float4*)&Bs[bK][bN] = bv;
        __syncthreads();

        #pragma unroll
        for (int kk = 0; kk < 8; kk++) {
            float4 a0 = *(const float4*)&As[kk][tr * 8];
            float4 a1 = *(const float4*)&As[kk][tr * 8 + 4];
            float4 b0 = *(const float4*)&Bs[kk][tc * 8];
            float4 b1 = *(const float4*)&Bs[kk][tc * 8 + 4];
            float a[8] = {a0.x, a0.y, a0.z, a0.w, a1.x, a1.y, a1.z, a1.w};
            float b[8] = {b0.x, b0.y, b0.z, b0.w, b1.x, b1.y, b1.z, b1.w};
            #pragma unroll
            for (int i = 0; i < 8; i++)
                #pragma unroll
                for (int j = 0; j < 8; j++)
                    acc[i][j] = fmaf(a[i], b[j], acc[i][j]);
        }
        __syncthreads();
    }

    // Epilogue
    #pragma unroll
    for (int i = 0; i < 8; i++) {
        int row = rowBase + tr * 8 + i;
        float* crow = C + (size_t)row * N;
        #pragma unroll
        for (int j = 0; j < 8; j += 4) {
            int col = colBase + tc * 8 + j;
            float4 bv = *(const float4*)&bias[col];
            float4 o;
            o.x = acc[i][j + 0] + bv.x;
            o.y = acc[i][j + 1] + bv.y;
            o.z = acc[i][j + 2] + bv.z;
            o.w = acc[i][j + 3] + bv.w;
            if (EPI == 1) {
                o.x = gelu_tanh(o.x); o.y = gelu_tanh(o.y);
                o.z = gelu_tanh(o.z); o.w = gelu_tanh(o.w);
            } else if (EPI == 2) {
                float4 rv = *(const float4*)&resid[(size_t)row * N + col];
                o.x += rv.x; o.y += rv.y; o.z += rv.z; o.w += rv.w;
            }
            *(float4*)&crow[col] = o;
        }
    }
}

// ---------------------------------------------------------------------------
// Attention scores: scores[b,h,q,k] = scale * dot(Q[b,q,h,:], K[b,k,h,:]) + bias(k)
// grid (S/64, S/64, B*NH), 256 threads, 4x4 micro-tile, full DH=64 in smem.
// ---------------------------------------------------------------------------
__global__ __launch_bounds__(256)
void attn_scores_k(const float* __restrict__ q, const float* __restrict__ k,
                   const int* __restrict__ amask, float* __restrict__ scores)
{
    const int bh = blockIdx.z;
    const int b  = bh / cNH;
    const int h  = bh % cNH;
    const int qBase = blockIdx.y * 64;
    const int kBase = blockIdx.x * 64;

    __shared__ float Qs[cDH][68];   // [d][q]  (transposed)
    __shared__ float Ks[cDH][68];   // [d][k]

    const int tid = threadIdx.x;

    #pragma unroll
    for (int it = 0; it < 4; it++) {
        int f   = tid + it * 256;       // float4 id 0..1023
        int row = f >> 4;               // 0..63
        int c4  = (f & 15) * 4;         // 0..60
        float4 qv = *(const float4*)&q[((size_t)(b * cS + qBase + row) * cNH + h) * cDH + c4];
        Qs[c4 + 0][row] = qv.x; Qs[c4 + 1][row] = qv.y;
        Qs[c4 + 2][row] = qv.z; Qs[c4 + 3][row] = qv.w;
        float4 kv = *(const float4*)&k[((size_t)(b * cS + kBase + row) * cNH + h) * cDH + c4];
        Ks[c4 + 0][row] = kv.x; Ks[c4 + 1][row] = kv.y;
        Ks[c4 + 2][row] = kv.z; Ks[c4 + 3][row] = kv.w;
    }
    __syncthreads();

    const int tr = tid >> 4;
    const int tc = tid & 15;
    float acc[4][4];
    #pragma unroll
    for (int i = 0; i < 4; i++)
        #pragma unroll
        for (int j = 0; j < 4; j++) acc[i][j] = 0.0f;

    #pragma unroll 8
    for (int dd = 0; dd < cDH; dd++) {
        float4 a = *(const float4*)&Qs[dd][tr * 4];
        float4 bb = *(const float4*)&Ks[dd][tc * 4];
        float av[4] = {a.x, a.y, a.z, a.w};
        float bv[4] = {bb.x, bb.y, bb.z, bb.w};
        #pragma unroll
        for (int i = 0; i < 4; i++)
            #pragma unroll
            for (int j = 0; j < 4; j++)
                acc[i][j] = fmaf(av[i], bv[j], acc[i][j]);
    }

    const float scale = 0.125f;  // 1/sqrt(64)
    #pragma unroll
    for (int i = 0; i < 4; i++) {
        int qi = qBase + tr * 4 + i;
        float* srow = scores + ((size_t)bh * cS + qi) * cS;
        #pragma unroll
        for (int j = 0; j < 4; j++) {
            int kj = kBase + tc * 4 + j;
            float biasv = (1.0f - (float)amask[b * cS + kj]) * -1e9f;
            srow[kj] = acc[i][j] * scale + biasv;
        }
    }
}

// ---------------------------------------------------------------------------
// Row softmax over last dim (512). grid = B*NH*S, 128 threads.
// ---------------------------------------------------------------------------
__global__ __launch_bounds__(128)
void softmax_k(float* __restrict__ scores)
{
    __shared__ float red[128];
    float* row = scores + (size_t)blockIdx.x * cS;
    const int tid = threadIdx.x;

    float v[4];
    #pragma unroll
    for (int i = 0; i < 4; i++) v[i] = row[tid + i * 128];

    float m = fmaxf(fmaxf(v[0], v[1]), fmaxf(v[2], v[3]));
    red[tid] = m;
    __syncthreads();
    for (int s2 = 64; s2 > 0; s2 >>= 1) {
        if (tid < s2) red[tid] = fmaxf(red[tid], red[tid + s2]);
        __syncthreads();
    }
    m = red[0];
    __syncthreads();

    float e[4], loc = 0.0f;
    #pragma unroll
    for (int i = 0; i < 4; i++) { e[i] = expf(v[i] - m); loc += e[i]; }
    red[tid] = loc;
    __syncthreads();
    for (int s2 = 64; s2 > 0; s2 >>= 1) {
        if (tid < s2) red[tid] += red[tid + s2];
        __syncthreads();
    }
    float inv = 1.0f / red[0];
    #pragma unroll
    for (int i = 0; i < 4; i++) row[tid + i * 128] = e[i] * inv;
}

// ---------------------------------------------------------------------------
// Context: ctx[b,q,h,d] = sum_k A[b,h,q,k] * V[b,k,h,d]
// grid (S/64, B*NH), 256 threads; block computes 64 q-rows x 64 d.
// ---------------------------------------------------------------------------
__global__ __launch_bounds__(256)
void attn_ctx_k(const float* __restrict__ scores, const float* __restrict__ v,
                float* __restrict__ ctx)
{
    const int bh = blockIdx.y;
    const int b  = bh / cNH;
    const int h  = bh % cNH;
    const int qBase = blockIdx.x * 64;

    __shared__ float As[64][68];   // As[k][q]  (transposed scores)
    __shared__ float Vs[64][68];   // Vs[k][d]

    const int tid = threadIdx.x;
    const int tr = tid >> 4;
    const int tc = tid & 15;

    float acc[4][4];
    #pragma unroll
    for (int i = 0; i < 4; i++)
        #pragma unroll
        for (int j = 0; j < 4; j++) acc[i][j] = 0.0f;

    for (int kt = 0; kt < cS; kt += 64) {
        #pragma unroll
        for (int it = 0; it < 4; it++) {
            int f   = tid + it * 256;
            int row = f >> 4;
            int c4  = (f & 15) * 4;
            float4 sv = *(const float4*)&scores[((size_t)bh * cS + qBase + row) * cS + kt + c4];
            As[c4 + 0][row] = sv.x; As[c4 + 1][row] = sv.y;
            As[c4 + 2][row] = sv.z; As[c4 + 3][row] = sv.w;
            float4 vv = *(const float4*)&v[((size_t)(b * cS + kt + row) * cNH + h) * cDH + c4];
            *(float4*)&Vs[row][c4] = vv;
        }
        __syncthreads();

        #pragma unroll 8
        for (int kk = 0; kk < 64; kk++) {
            float4 a = *(const float4*)&As[kk][tr * 4];
            float4 bb = *(const float4*)&Vs[kk][tc * 4];
            float av[4] = {a.x, a.y, a.z, a.w};
            float bv[4] = {bb.x, bb.y, bb.z, bb.w};
            #pragma unroll
            for (int i = 0; i < 4; i++)
                #pragma unroll
                for (int j = 0; j < 4; j++)
                    acc[i][j] = fmaf(av[i], bv[j], acc[i][j]);
        }
        __syncthreads();
    }

    #pragma unroll
    for (int i = 0; i < 4; i++) {
        int qi = qBase + tr * 4 + i;
        #pragma unroll
        for (int j = 0; j < 4; j++) {
            int d = tc * 4 + j;
            ctx[((size_t)(b * cS + qi) * cNH + h) * cDH + d] = acc[i][j];
        }
    }
}

// ---------------------------------------------------------------------------
// LayerNorm over last dim (768). grid = B*S, 256 threads. out = (x-m)*rstd*s + b
// ---------------------------------------------------------------------------
__global__ __launch_bounds__(256)
void ln_k(const float* __restrict__ in, const float* __restrict__ s,
          const float* __restrict__ bp, float* __restrict__ out)
{
    __shared__ float red[256];
    const float* xr = in + (size_t)blockIdx.x * cH;
    float* orow = out + (size_t)blockIdx.x * cH;
    const int tid = threadIdx.x;

    float v0 = xr[tid], v1 = xr[tid + 256], v2 = xr[tid + 512];
    red[tid] = v0 + v1 + v2;
    __syncthreads();
    for (int s2 = 128; s2 > 0; s2 >>= 1) {
        if (tid < s2) red[tid] += red[tid + s2];
        __syncthreads();
    }
    float m = red[0] * (1.0f / (float)cH);
    __syncthreads();

    float d0 = v0 - m, d1 = v1 - m, d2 = v2 - m;
    red[tid] = d0 * d0 + d1 * d1 + d2 * d2;
    __syncthreads();
    for (int s2 = 128; s2 > 0; s2 >>= 1) {
        if (tid < s2) red[tid] += red[tid + s2];
        __syncthreads();
    }
    float var = red[0] * (1.0f / (float)cH);
    float r = rsqrtf(var + 1e-12f);

    orow[tid]       = d0 * r * s[tid]       + bp[tid];
    orow[tid + 256] = d1 * r * s[tid + 256] + bp[tid + 256];
    orow[tid + 512] = d2 * r * s[tid + 512] + bp[tid + 512];
}

// ---------------------------------------------------------------------------
// Embedding: out[b,s,:] = token_emb[ids[b,s],:] + pos_emb[s,:]
// ---------------------------------------------------------------------------
__global__ void embed_k(const int* __restrict__ ids, const float* __restrict__ te,
                        const float* __restrict__ pe, float* __restrict__ out)
{
    const int bs = blockIdx.x;
    const int s2 = bs % cS;
    const int id = ids[bs];
    for (int h = threadIdx.x; h < cH; h += blockDim.x)
        out[(size_t)bs * cH + h] = te[(size_t)id * cH + h] + pe[s2 * cH + h];
}

// ---------------------------------------------------------------------------
// Classifier: logits[row, j] = dot(x[row,:], cls_W[:,j]) + cls_b[j]   (N=19)
// grid = B*S, 128 threads (4 warps), warp w handles cols w, w+4, ...
// ---------------------------------------------------------------------------
__global__ __launch_bounds__(128)
void cls_k(const float* __restrict__ x, const float* __restrict__ W,
           const float* __restrict__ bias, float* __restrict__ logits)
{
    __shared__ float xs[cH];
    const int row = blockIdx.x;
    const int tid = threadIdx.x;
    for (int h = tid; h < cH; h += 128) xs[h] = x[(size_t)row * cH + h];
    __syncthreads();

    const int warp = tid >> 5, lane = tid & 31;
    for (int j = warp; j < cNL; j += 4) {
        float sum = 0.0f;
        for (int k2 = lane; k2 < cH; k2 += 32)
            sum = fmaf(xs[k2], W[k2 * cNL + j], sum);
        #pragma unroll
        for (int o = 16; o > 0; o >>= 1)
            sum += __shfl_down_sync(0xffffffffu, sum, o);
        if (lane == 0) logits[(size_t)row * cNL + j] = sum + bias[j];
    }
}

// ---------------------------------------------------------------------------
// CRF: numerator + forward algorithm per batch. grid = B, 32 threads.
// ---------------------------------------------------------------------------
__global__ __launch_bounds__(32)
void crf_k(const float* __restrict__ logits, const int* __restrict__ labels,
           const int* __restrict__ amask, const float* __restrict__ startT,
           const float* __restrict__ endT, const float* __restrict__ trans,
           float* __restrict__ pb)
{
    const int b = blockIdx.x;
    const int j = threadIdx.x;

    __shared__ float tT[cNL][cNL + 1];   // tT[j][i] = trans[i][j]
    __shared__ float alpha[cNL];
    __shared__ float num_s;

    for (int idx = j; idx < cNL * cNL; idx += 32) {
        int i = idx / cNL, jj = idx % cNL;
        tT[jj][i] = trans[idx];
    }

    const int* lab = labels + b * cS;
    const int* mk  = amask + b * cS;
    const float* lg = logits + (size_t)b * cS * cNL;

    if (j == 0) {
        float num = startT[lab[0]] + lg[lab[0]];
        float msum = (float)mk[0];
        for (int t = 1; t < cS; t++) {
            float mf = (float)mk[t];
            num += (trans[lab[t - 1] * cNL + lab[t]] + lg[t * cNL + lab[t]]) * mf;
            msum += mf;
        }
        int last = (int)msum - 1;
        num += endT[lab[last]];
        num_s = num;
    }
    __syncthreads();

    if (j < cNL) alpha[j] = startT[j] + lg[j];
    __syncthreads();

    for (int t = 1; t < cS; t++) {
        float nv = 0.0f;
        if (j < cNL) {
            float m = -1e30f;
            #pragma unroll
            for (int i = 0; i < cNL; i++) m = fmaxf(m, alpha[i] + tT[j][i]);
            float ss = 0.0f;
            #pragma unroll
            for (int i = 0; i < cNL; i++) ss += expf(alpha[i] + tT[j][i] - m);
            float nxt = m + logf(ss) + lg[t * cNL + j];
            nv = ((float)mk[t] > 0.0f) ? nxt : alpha[j];
        }
        __syncthreads();
        if (j < cNL) alpha[j] = nv;
        __syncthreads();
    }

    if (j == 0) {
        float m = -1e30f;
        #pragma unroll
        for (int jj = 0; jj < cNL; jj++) m = fmaxf(m, alpha[jj] + endT[jj]);
        float ss = 0.0f;
        #pragma unroll
        for (int jj = 0; jj < cNL; jj++) ss += expf(alpha[jj] + endT[jj] - m);
        pb[b] = (m + logf(ss)) - num_s;
    }
}

__global__ void final_k(const float* __restrict__ pb, float* __restrict__ out)
{
    float s2 = 0.0f;
    for (int b2 = 0; b2 < cB; b2++) s2 += pb[b2];
    out[0] = s2;
}

// ---------------------------------------------------------------------------
// Launch
// ---------------------------------------------------------------------------
extern "C" void kernel_launch(void* const* d_in, const int* in_sizes, int n_in,
                              void* d_out, int out_size)
{
    const int*   ids       = (const int*)d_in[0];
    const int*   amask     = (const int*)d_in[1];
    const int*   labels    = (const int*)d_in[2];
    const float* token_emb = (const float*)d_in[3];
    const float* pos_emb   = (const float*)d_in[4];
    const float* ln_emb_s  = (const float*)d_in[5];
    const float* ln_emb_b  = (const float*)d_in[6];
    const float* Wq        = (const float*)d_in[7];
    const float* bq        = (const float*)d_in[8];
    const float* Wk        = (const float*)d_in[9];
    const float* bk        = (const float*)d_in[10];
    const float* Wv        = (const float*)d_in[11];
    const float* bv        = (const float*)d_in[12];
    const float* Wo        = (const float*)d_in[13];
    const float* bo        = (const float*)d_in[14];
    const float* ln1_s     = (const float*)d_in[15];
    const float* ln1_b     = (const float*)d_in[16];
    const float* W1        = (const float*)d_in[17];
    const float* b1        = (const float*)d_in[18];
    const float* W2        = (const float*)d_in[19];
    const float* b2        = (const float*)d_in[20];
    const float* ln2_s     = (const float*)d_in[21];
    const float* ln2_b     = (const float*)d_in[22];
    const float* cls_W     = (const float*)d_in[23];
    const float* cls_b     = (const float*)d_in[24];
    const float* startT    = (const float*)d_in[25];
    const float* endT      = (const float*)d_in[26];
    const float* trans     = (const float*)d_in[27];

    float *px, *ptmp, *pq, *pk, *pv, *pctx, *pffn, *pscores, *plogits, *ppb;
    cudaGetSymbolAddress((void**)&px, g_x);
    cudaGetSymbolAddress((void**)&ptmp, g_tmp);
    cudaGetSymbolAddress((void**)&pq, g_q);
    cudaGetSymbolAddress((void**)&pk, g_k);
    cudaGetSymbolAddress((void**)&pv, g_v);
    cudaGetSymbolAddress((void**)&pctx, g_ctx);
    cudaGetSymbolAddress((void**)&pffn, g_ffn);
    cudaGetSymbolAddress((void**)&pscores, g_scores);
    cudaGetSymbolAddress((void**)&plogits, g_logits);
    cudaGetSymbolAddress((void**)&ppb, g_pb);

    // Embedding + LN
    embed_k<<<cM, 256>>>(ids, token_emb, pos_emb, ptmp);
    ln_k<<<cM, 256>>>(ptmp, ln_emb_s, ln_emb_b, px);

    const dim3 gHH(cH / 128, cM / 128);     // (6, 32)
    const dim3 gHF(cDFF / 128, cM / 128);   // (24, 32)
    const dim3 gSc(cS / 64, cS / 64, cB * cNH);
    const dim3 gCx(cS / 64, cB * cNH);

    for (int l = 0; l < cL; l++) {
        const float* Wq_l = Wq + (size_t)l * cH * cH;
        const float* Wk_l = Wk + (size_t)l * cH * cH;
        const float* Wv_l = Wv + (size_t)l * cH * cH;
        const float* Wo_l = Wo + (size_t)l * cH * cH;
        const float* W1_l = W1 + (size_t)l * cH * cDFF;
        const float* W2_l = W2 + (size_t)l * cDFF * cH;

        sgemm_k<0><<<gHH, 256>>>(px, Wq_l, bq + l * cH, nullptr, pq, cM, cH, cH);
        sgemm_k<0><<<gHH, 256>>>(px, Wk_l, bk + l * cH, nullptr, pk, cM, cH, cH);
        sgemm_k<0><<<gHH, 256>>>(px, Wv_l, bv + l * cH, nullptr, pv, cM, cH, cH);

        attn_scores_k<<<gSc, 256>>>(pq, pk, amask, pscores);
        softmax_k<<<cB * cNH * cS, 128>>>(pscores);
        attn_ctx_k<<<gCx, 256>>>(pscores, pv, pctx);

        sgemm_k<2><<<gHH, 256>>>(pctx, Wo_l, bo + l * cH, px, ptmp, cM, cH, cH);
        ln_k<<<cM, 256>>>(ptmp, ln1_s + l * cH, ln1_b + l * cH, px);

        sgemm_k<1><<<gHF, 256>>>(px, W1_l, b1 + l * cDFF, nullptr, pffn, cM, cDFF, cH);
        sgemm_k<2><<<gHH, 256>>>(pffn, W2_l, b2 + l * cH, px, ptmp, cM, cH, cDFF);
        ln_k<<<cM, 256>>>(ptmp, ln2_s + l * cH, ln2_b + l * cH, px);
    }

    cls_k<<<cM, 128>>>(px, cls_W, cls_b, plogits);
    crf_k<<<cB, 32>>>(plogits, labels, amask, startT, endT, trans, ppb);
    final_k<<<1, 1>>>(ppb, (float*)d_out);
}

// round 2
// speedup vs baseline: 2.9763x; 2.9763x over previous
#include <cuda_runtime.h>
#include <cuda_bf16.h>
#include <math.h>

// Problem constants
#define cB   8
#define cS   512
#define cH   768
#define cL   12
#define cNH  12
#define cDH  64
#define cDFF 3072
#define cNL  19
#define cM   (cB * cS)   // 4096 rows

// ---------------------------------------------------------------------------
// Scratch (static device globals; no allocations anywhere)
// ---------------------------------------------------------------------------
__device__ float g_x   [cM * cH];
__device__ float g_tmp [cM * cH];
__device__ float g_q   [cM * cH];
__device__ float g_k   [cM * cH];
__device__ float g_v   [cM * cH];
__device__ float g_ctx [cM * cH];
__device__ float g_ffn [cM * cDFF];
__device__ float g_scores[(size_t)cB * cNH * cS * cS];
__device__ float g_logits[cM * cNL];
__device__ float g_pb  [cB];

// ---------------------------------------------------------------------------
// Helpers
// ---------------------------------------------------------------------------
__device__ __forceinline__ float gelu_tanh(float x) {
    float c = 0.7978845608028654f * (x + 0.044715f * x * x * x);
    return 0.5f * x * (1.0f + tanhf(c));
}

__device__ __forceinline__ void cp16(void* smem, const void* gmem) {
    unsigned a = (unsigned)__cvta_generic_to_shared(smem);
    asm volatile("cp.async.cg.shared.global [%0], [%1], 16;\n" :: "r"(a), "l"(gmem));
}
#define CP_COMMIT asm volatile("cp.async.commit_group;\n" ::: "memory")
#define CP_WAIT0  asm volatile("cp.async.wait_group 0;\n" ::: "memory")

// m16n8k8 TF32 mma, fp32 accumulate
__device__ __forceinline__ void mma8(float* c, const unsigned* a, const unsigned* b) {
    asm volatile(
        "mma.sync.aligned.m16n8k8.row.col.f32.tf32.tf32.f32 "
        "{%0,%1,%2,%3},{%4,%5,%6,%7},{%8,%9},{%0,%1,%2,%3};\n"
        : "+f"(c[0]), "+f"(c[1]), "+f"(c[2]), "+f"(c[3])
        : "r"(a[0]), "r"(a[1]), "r"(a[2]), "r"(a[3]), "r"(b[0]), "r"(b[1]));
}

// ---------------------------------------------------------------------------
// TF32 tensor-core GEMM body: C[M,N] = A[M,K] @ B[K,N] (+bias, epilogues)
// 128x128 tile, BK=16, 256 threads (8 warps: 2x4), warp tile 64x32.
// EPI: 0 = bias, 1 = bias+gelu, 2 = bias+residual
// ---------------------------------------------------------------------------
template <int EPI>
__device__ __forceinline__ void gemm_body(
    const float* __restrict__ A, const float* __restrict__ Bm,
    const float* __restrict__ bias, const float* __restrict__ resid,
    float* __restrict__ C, int N, int K, int rowBase, int colBase)
{
    __shared__ float As[2][128][20];    // [m][k], stride 20 -> conflict-free frags
    __shared__ float Bs[2][16][136];    // [k][n], stride 136 -> conflict-free frags

    const int tid  = threadIdx.x;
    const int lane = tid & 31;
    const int warp = tid >> 5;
    const int wm   = warp >> 2;   // 0..1
    const int wn   = warp & 3;    // 0..3

    float acc[4][4][4];
    #pragma unroll
    for (int i = 0; i < 4; i++)
        #pragma unroll
        for (int j = 0; j < 4; j++)
            #pragma unroll
            for (int r = 0; r < 4; r++) acc[i][j][r] = 0.0f;

    auto issue = [&](int s, int kt) {
        const int k0 = kt * 16;
        #pragma unroll
        for (int j = 0; j < 2; j++) {
            int idx = tid + j * 256;
            int r = idx >> 2, c = (idx & 3) * 4;
            cp16(&As[s][r][c], A + (size_t)(rowBase + r) * K + k0 + c);
        }
        #pragma unroll
        for (int j = 0; j < 2; j++) {
            int idx = tid + j * 256;
            int kk = idx >> 5, c = (idx & 31) * 4;
            cp16(&Bs[s][kk][c], Bm + (size_t)(k0 + kk) * N + colBase + c);
        }
    };

    const int nK = K / 16;
    issue(0, 0); CP_COMMIT;

    for (int kt = 0; kt < nK; kt++) {
        CP_WAIT0;
        __syncthreads();
        if (kt + 1 < nK) { issue((kt + 1) & 1, kt + 1); CP_COMMIT; }
        const int s = kt & 1;

        #pragma unroll
        for (int ks = 0; ks < 2; ks++) {
            const int kk = ks * 8 + (lane & 3);
            unsigned af[4][4], bf[4][2];
            #pragma unroll
            for (int mt = 0; mt < 4; mt++) {
                int m = wm * 64 + mt * 16 + (lane >> 2);
                af[mt][0] = __float_as_uint(As[s][m    ][kk    ]);
                af[mt][1] = __float_as_uint(As[s][m + 8][kk    ]);
                af[mt][2] = __float_as_uint(As[s][m    ][kk + 4]);
                af[mt][3] = __float_as_uint(As[s][m + 8][kk + 4]);
            }
            #pragma unroll
            for (int nt = 0; nt < 4; nt++) {
                int n = wn * 32 + nt * 8 + (lane >> 2);
                bf[nt][0] = __float_as_uint(Bs[s][kk    ][n]);
                bf[nt][1] = __float_as_uint(Bs[s][kk + 4][n]);
            }
            #pragma unroll
            for (int mt = 0; mt < 4; mt++)
                #pragma unroll
                for (int nt = 0; nt < 4; nt++)
                    mma8(acc[mt][nt], af[mt], bf[nt]);
        }
        __syncthreads();
    }

    // Epilogue
    #pragma unroll
    for (int mt = 0; mt < 4; mt++) {
        #pragma unroll
        for (int nt = 0; nt < 4; nt++) {
            int col = colBase + wn * 32 + nt * 8 + 2 * (lane & 3);
            float2 bv = *(const float2*)&bias[col];
            #pragma unroll
            for (int h = 0; h < 2; h++) {
                int row = rowBase + wm * 64 + mt * 16 + (lane >> 2) + h * 8;
                float ox = acc[mt][nt][h * 2 + 0] + bv.x;
                float oy = acc[mt][nt][h * 2 + 1] + bv.y;
                if (EPI == 1) { ox = gelu_tanh(ox); oy = gelu_tanh(oy); }
                else if (EPI == 2) {
                    float2 rv = *(const float2*)&resid[(size_t)row * N + col];
                    ox += rv.x; oy += rv.y;
                }
                *(float2*)&C[(size_t)row * N + col] = make_float2(ox, oy);
            }
        }
    }
}

template <int EPI>
__global__ __launch_bounds__(256)
void gemm_k(const float* __restrict__ A, const float* __restrict__ Bm,
            const float* __restrict__ bias, const float* __restrict__ resid,
            float* __restrict__ C, int N, int K)
{
    gemm_body<EPI>(A, Bm, bias, resid, C, N, K, blockIdx.y * 128, blockIdx.x * 128);
}

// Fused QKV: grid.z selects the projection; shares the A tile in L2.
__global__ __launch_bounds__(256)
void qkv_k(const float* __restrict__ x,
           const float* __restrict__ Wq, const float* __restrict__ Wk, const float* __restrict__ Wv,
           const float* __restrict__ bq, const float* __restrict__ bk, const float* __restrict__ bv,
           float* __restrict__ q, float* __restrict__ k, float* __restrict__ v,
           int N, int K)
{
    const float* W; const float* bb; float* o;
    if (blockIdx.z == 0)      { W = Wq; bb = bq; o = q; }
    else if (blockIdx.z == 1) { W = Wk; bb = bk; o = k; }
    else                      { W = Wv; bb = bv; o = v; }
    gemm_body<0>(x, W, bb, nullptr, o, N, K, blockIdx.y * 128, blockIdx.x * 128);
}

// ---------------------------------------------------------------------------
// Attention scores (TF32 mma): scores[b,h,q,k] = scale*dot(Q,K) + maskbias
// grid (S/64, S/64, B*NH), 128 threads (4 warps, each 16 q-rows x 64 k-cols)
// ---------------------------------------------------------------------------
__global__ __launch_bounds__(128)
void attn_scores_mma(const float* __restrict__ q, const float* __restrict__ k,
                     const int* __restrict__ amask, float* __restrict__ scores)
{
    const int bh = blockIdx.z, b = bh / cNH, h = bh % cNH;
    const int qBase = blockIdx.y * 64, kBase = blockIdx.x * 64;

    __shared__ float Qs[64][68];   // [token][d]
    __shared__ float Ks[64][68];

    const int tid = threadIdx.x, lane = tid & 31, warp = tid >> 5;

    #pragma unroll
    for (int j = 0; j < 8; j++) {
        int f = tid + j * 128;
        int row = f >> 4, c4 = (f & 15) * 4;
        *(float4*)&Qs[row][c4] =
            *(const float4*)&q[((size_t)(b * cS + qBase + row) * cNH + h) * cDH + c4];
        *(float4*)&Ks[row][c4] =
            *(const float4*)&k[((size_t)(b * cS + kBase + row) * cNH + h) * cDH + c4];
    }
    __syncthreads();

    float acc[8][4] = {};
    #pragma unroll
    for (int ks = 0; ks < 8; ks++) {
        const int kk = ks * 8 + (lane & 3);
        unsigned af[4];
        int m = 16 * warp + (lane >> 2);
        af[0] = __float_as_uint(Qs[m    ][kk    ]);
        af[1] = __float_as_uint(Qs[m + 8][kk    ]);
        af[2] = __float_as_uint(Qs[m    ][kk + 4]);
        af[3] = __float_as_uint(Qs[m + 8][kk + 4]);
        #pragma unroll
        for (int nt = 0; nt < 8; nt++) {
            unsigned bf[2];
            int n = nt * 8 + (lane >> 2);
            bf[0] = __float_as_uint(Ks[n][kk    ]);
            bf[1] = __float_as_uint(Ks[n][kk + 4]);
            mma8(acc[nt], af, bf);
        }
    }

    const float scale = 0.125f;
    #pragma unroll
    for (int nt = 0; nt < 8; nt++) {
        int col = kBase + nt * 8 + 2 * (lane & 3);
        float m0 = (1.0f - (float)amask[b * cS + col    ]) * -1e9f;
        float m1 = (1.0f - (float)amask[b * cS + col + 1]) * -1e9f;
        #pragma unroll
        for (int hh = 0; hh < 2; hh++) {
            int row = qBase + 16 * warp + (lane >> 2) + hh * 8;
            float* sp = scores + ((size_t)bh * cS + row) * cS + col;
            sp[0] = acc[nt][hh * 2 + 0] * scale + m0;
            sp[1] = acc[nt][hh * 2 + 1] * scale + m1;
        }
    }
}

// ---------------------------------------------------------------------------
// Context (TF32 mma): ctx[b,q,h,d] = sum_k A[b,h,q,k] * V[b,k,h,d]
// grid (S/64, B*NH), 128 threads
// ---------------------------------------------------------------------------
__global__ __launch_bounds__(128)
void attn_ctx_mma(const float* __restrict__ scores, const float* __restrict__ v,
                  float* __restrict__ ctx)
{
    const int bh = blockIdx.y, b = bh / cNH, h = bh % cNH;
    const int qBase = blockIdx.x * 64;

    __shared__ float As_[64][68];   // [q][k]
    __shared__ float Vs [64][72];   // [k][d]

    const int tid = threadIdx.x, lane = tid & 31, warp = tid >> 5;

    float acc[8][4] = {};
    for (int kt = 0; kt < cS; kt += 64) {
        #pragma unroll
        for (int j = 0; j < 8; j++) {
            int f = tid + j * 128;
            int row = f >> 4, c4 = (f & 15) * 4;
            *(float4*)&As_[row][c4] =
                *(const float4*)&scores[((size_t)bh * cS + qBase + row) * cS + kt + c4];
            *(float4*)&Vs[row][c4] =
                *(const float4*)&v[((size_t)(b * cS + kt + row) * cNH + h) * cDH + c4];
        }
        __syncthreads();

        #pragma unroll
        for (int ks = 0; ks < 8; ks++) {
            const int kk = ks * 8 + (lane & 3);
            unsigned af[4];
            int m = 16 * warp + (lane >> 2);
            af[0] = __float_as_uint(As_[m    ][kk    ]);
            af[1] = __float_as_uint(As_[m + 8][kk    ]);
            af[2] = __float_as_uint(As_[m    ][kk + 4]);
            af[3] = __float_as_uint(As_[m + 8][kk + 4]);
            #pragma unroll
            for (int nt = 0; nt < 8; nt++) {
                unsigned bf[2];
                int n = nt * 8 + (lane >> 2);
                bf[0] = __float_as_uint(Vs[kk    ][n]);
                bf[1] = __float_as_uint(Vs[kk + 4][n]);
                mma8(acc[nt], af, bf);
            }
        }
        __syncthreads();
    }

    #pragma unroll
    for (int nt = 0; nt < 8; nt++) {
        int d = nt * 8 + 2 * (lane & 3);
        #pragma unroll
        for (int hh = 0; hh < 2; hh++) {
            int row = qBase + 16 * warp + (lane >> 2) + hh * 8;
            float* cp = ctx + ((size_t)(b * cS + row) * cNH + h) * cDH + d;
            cp[0] = acc[nt][hh * 2 + 0];
            cp[1] = acc[nt][hh * 2 + 1];
        }
    }
}

// ---------------------------------------------------------------------------
// Row softmax over last dim (512). grid = B*NH*S, 128 threads.
// ---------------------------------------------------------------------------
__global__ __launch_bounds__(128)
void softmax_k(float* __restrict__ scores)
{
    __shared__ float red[128];
    float* row = scores + (size_t)blockIdx.x * cS;
    const int tid = threadIdx.x;

    float v[4];
    #pragma unroll
    for (int i = 0; i < 4; i++) v[i] = row[tid + i * 128];

    float m = fmaxf(fmaxf(v[0], v[1]), fmaxf(v[2], v[3]));
    red[tid] = m;
    __syncthreads();
    for (int s2 = 64; s2 > 0; s2 >>= 1) {
        if (tid < s2) red[tid] = fmaxf(red[tid], red[tid + s2]);
        __syncthreads();
    }
    m = red[0];
    __syncthreads();

    float e[4], loc = 0.0f;
    #pragma unroll
    for (int i = 0; i < 4; i++) { e[i] = expf(v[i] - m); loc += e[i]; }
    red[tid] = loc;
    __syncthreads();
    for (int s2 = 64; s2 > 0; s2 >>= 1) {
        if (tid < s2) red[tid] += red[tid + s2];
        __syncthreads();
    }
    float inv = 1.0f / red[0];
    #pragma unroll
    for (int i = 0; i < 4; i++) row[tid + i * 128] = e[i] * inv;
}

// ---------------------------------------------------------------------------
// LayerNorm over last dim (768). grid = B*S, 256 threads.
// ---------------------------------------------------------------------------
__global__ __launch_bounds__(256)
void ln_k(const float* __restrict__ in, const float* __restrict__ s,
          const float* __restrict__ bp, float* __restrict__ out)
{
    __shared__ float red[256];
    const float* xr = in + (size_t)blockIdx.x * cH;
    float* orow = out + (size_t)blockIdx.x * cH;
    const int tid = threadIdx.x;

    float v0 = xr[tid], v1 = xr[tid + 256], v2 = xr[tid + 512];
    red[tid] = v0 + v1 + v2;
    __syncthreads();
    for (int s2 = 128; s2 > 0; s2 >>= 1) {
        if (tid < s2) red[tid] += red[tid + s2];
        __syncthreads();
    }
    float m = red[0] * (1.0f / (float)cH);
    __syncthreads();

    float d0 = v0 - m, d1 = v1 - m, d2 = v2 - m;
    red[tid] = d0 * d0 + d1 * d1 + d2 * d2;
    __syncthreads();
    for (int s2 = 128; s2 > 0; s2 >>= 1) {
        if (tid < s2) red[tid] += red[tid + s2];
        __syncthreads();
    }
    float var = red[0] * (1.0f / (float)cH);
    float r = rsqrtf(var + 1e-12f);

    orow[tid]       = d0 * r * s[tid]       + bp[tid];
    orow[tid + 256] = d1 * r * s[tid + 256] + bp[tid + 256];
    orow[tid + 512] = d2 * r * s[tid + 512] + bp[tid + 512];
}

// ---------------------------------------------------------------------------
// Embedding
// ---------------------------------------------------------------------------
__global__ void embed_k(const int* __restrict__ ids, const float* __restrict__ te,
                        const float* __restrict__ pe, float* __restrict__ out)
{
    const int bs = blockIdx.x;
    const int s2 = bs % cS;
    const int id = ids[bs];
    for (int h = threadIdx.x; h < cH; h += blockDim.x)
        out[(size_t)bs * cH + h] = te[(size_t)id * cH + h] + pe[s2 * cH + h];
}

// ---------------------------------------------------------------------------
// Classifier (N=19)
// ---------------------------------------------------------------------------
__global__ __launch_bounds__(128)
void cls_k(const float* __restrict__ x, const float* __restrict__ W,
           const float* __restrict__ bias, float* __restrict__ logits)
{
    __shared__ float xs[cH];
    const int row = blockIdx.x;
    const int tid = threadIdx.x;
    for (int h = tid; h < cH; h += 128) xs[h] = x[(size_t)row * cH + h];
    __syncthreads();

    const int warp = tid >> 5, lane = tid & 31;
    for (int j = warp; j < cNL; j += 4) {
        float sum = 0.0f;
        for (int k2 = lane; k2 < cH; k2 += 32)
            sum = fmaf(xs[k2], W[k2 * cNL + j], sum);
        #pragma unroll
        for (int o = 16; o > 0; o >>= 1)
            sum += __shfl_down_sync(0xffffffffu, sum, o);
        if (lane == 0) logits[(size_t)row * cNL + j] = sum + bias[j];
    }
}

// ---------------------------------------------------------------------------
// CRF
// ---------------------------------------------------------------------------
__global__ __launch_bounds__(32)
void crf_k(const float* __restrict__ logits, const int* __restrict__ labels,
           const int* __restrict__ amask, const float* __restrict__ startT,
           const float* __restrict__ endT, const float* __restrict__ trans,
           float* __restrict__ pb)
{
    const int b = blockIdx.x;
    const int j = threadIdx.x;

    __shared__ float tT[cNL][cNL + 1];
    __shared__ float alpha[cNL];
    __shared__ float num_s;

    for (int idx = j; idx < cNL * cNL; idx += 32) {
        int i = idx / cNL, jj = idx % cNL;
        tT[jj][i] = trans[idx];
    }

    const int* lab = labels + b * cS;
    const int* mk  = amask + b * cS;
    const float* lg = logits + (size_t)b * cS * cNL;

    if (j == 0) {
        float num = startT[lab[0]] + lg[lab[0]];
        float msum = (float)mk[0];
        for (int t = 1; t < cS; t++) {
            float mf = (float)mk[t];
            num += (trans[lab[t - 1] * cNL + lab[t]] + lg[t * cNL + lab[t]]) * mf;
            msum += mf;
        }
        int last = (int)msum - 1;
        num += endT[lab[last]];
        num_s = num;
    }
    __syncthreads();

    if (j < cNL) alpha[j] = startT[j] + lg[j];
    __syncthreads();

    for (int t = 1; t < cS; t++) {
        float nv = 0.0f;
        if (j < cNL) {
            float m = -1e30f;
            #pragma unroll
            for (int i = 0; i < cNL; i++) m = fmaxf(m, alpha[i] + tT[j][i]);
            float ss = 0.0f;
            #pragma unroll
            for (int i = 0; i < cNL; i++) ss += expf(alpha[i] + tT[j][i] - m);
            float nxt = m + logf(ss) + lg[t * cNL + j];
            nv = ((float)mk[t] > 0.0f) ? nxt : alpha[j];
        }
        __syncthreads();
        if (j < cNL) alpha[j] = nv;
        __syncthreads();
    }

    if (j == 0) {
        float m = -1e30f;
        #pragma unroll
        for (int jj = 0; jj < cNL; jj++) m = fmaxf(m, alpha[jj] + endT[jj]);
        float ss = 0.0f;
        #pragma unroll
        for (int jj = 0; jj < cNL; jj++) ss += expf(alpha[jj] + endT[jj] - m);
        pb[b] = (m + logf(ss)) - num_s;
    }
}

__global__ void final_k(const float* __restrict__ pb, float* __restrict__ out)
{
    float s2 = 0.0f;
    for (int b2 = 0; b2 < cB; b2++) s2 += pb[b2];
    out[0] = s2;
}

// ---------------------------------------------------------------------------
// Launch
// ---------------------------------------------------------------------------
extern "C" void kernel_launch(void* const* d_in, const int* in_sizes, int n_in,
                              void* d_out, int out_size)
{
    const int*   ids       = (const int*)d_in[0];
    const int*   amask     = (const int*)d_in[1];
    const int*   labels    = (const int*)d_in[2];
    const float* token_emb = (const float*)d_in[3];
    const float* pos_emb   = (const float*)d_in[4];
    const float* ln_emb_s  = (const float*)d_in[5];
    const float* ln_emb_b  = (const float*)d_in[6];
    const float* Wq        = (const float*)d_in[7];
    const float* bq        = (const float*)d_in[8];
    const float* Wk        = (const float*)d_in[9];
    const float* bk        = (const float*)d_in[10];
    const float* Wv        = (const float*)d_in[11];
    const float* bv        = (const float*)d_in[12];
    const float* Wo        = (const float*)d_in[13];
    const float* bo        = (const float*)d_in[14];
    const float* ln1_s     = (const float*)d_in[15];
    const float* ln1_b     = (const float*)d_in[16];
    const float* W1        = (const float*)d_in[17];
    const float* b1        = (const float*)d_in[18];
    const float* W2        = (const float*)d_in[19];
    const float* b2        = (const float*)d_in[20];
    const float* ln2_s     = (const float*)d_in[21];
    const float* ln2_b     = (const float*)d_in[22];
    const float* cls_W     = (const float*)d_in[23];
    const float* cls_b     = (const float*)d_in[24];
    const float* startT    = (const float*)d_in[25];
    const float* endT      = (const float*)d_in[26];
    const float* trans     = (const float*)d_in[27];

    float *px, *ptmp, *pq, *pk, *pv, *pctx, *pffn, *pscores, *plogits, *ppb;
    cudaGetSymbolAddress((void**)&px, g_x);
    cudaGetSymbolAddress((void**)&ptmp, g_tmp);
    cudaGetSymbolAddress((void**)&pq, g_q);
    cudaGetSymbolAddress((void**)&pk, g_k);
    cudaGetSymbolAddress((void**)&pv, g_v);
    cudaGetSymbolAddress((void**)&pctx, g_ctx);
    cudaGetSymbolAddress((void**)&pffn, g_ffn);
    cudaGetSymbolAddress((void**)&pscores, g_scores);
    cudaGetSymbolAddress((void**)&plogits, g_logits);
    cudaGetSymbolAddress((void**)&ppb, g_pb);

    embed_k<<<cM, 256>>>(ids, token_emb, pos_emb, ptmp);
    ln_k<<<cM, 256>>>(ptmp, ln_emb_s, ln_emb_b, px);

    const dim3 gQKV(cH / 128, cM / 128, 3);   // (6, 32, 3)
    const dim3 gHH (cH / 128, cM / 128);      // (6, 32)
    const dim3 gHF (cDFF / 128, cM / 128);    // (24, 32)
    const dim3 gSc (cS / 64, cS / 64, cB * cNH);
    const dim3 gCx (cS / 64, cB * cNH);

    for (int l = 0; l < cL; l++) {
        const float* Wq_l = Wq + (size_t)l * cH * cH;
        const float* Wk_l = Wk + (size_t)l * cH * cH;
        const float* Wv_l = Wv + (size_t)l * cH * cH;
        const float* Wo_l = Wo + (size_t)l * cH * cH;
        const float* W1_l = W1 + (size_t)l * cH * cDFF;
        const float* W2_l = W2 + (size_t)l * cDFF * cH;

        qkv_k<<<gQKV, 256>>>(px, Wq_l, Wk_l, Wv_l,
                             bq + l * cH, bk + l * cH, bv + l * cH,
                             pq, pk, pv, cH, cH);

        attn_scores_mma<<<gSc, 128>>>(pq, pk, amask, pscores);
        softmax_k<<<cB * cNH * cS, 128>>>(pscores);
        attn_ctx_mma<<<gCx, 128>>>(pscores, pv, pctx);

        gemm_k<2><<<gHH, 256>>>(pctx, Wo_l, bo + l * cH, px, ptmp, cH, cH);
        ln_k<<<cM, 256>>>(ptmp, ln1_s + l * cH, ln1_b + l * cH, px);

        gemm_k<1><<<gHF, 256>>>(px, W1_l, b1 + l * cDFF, nullptr, pffn, cDFF, cH);
        gemm_k<2><<<gHH, 256>>>(pffn, W2_l, b2 + l * cH, px, ptmp, cH, cDFF);
        ln_k<<<cM, 256>>>(ptmp, ln2_s + l * cH, ln2_b + l * cH, px);
    }

    cls_k<<<cM, 128>>>(px, cls_W, cls_b, plogits);
    crf_k<<<cB, 32>>>(plogits, labels, amask, startT, endT, trans, ppb);
    final_k<<<1, 1>>>(ppb, (float*)d_out);
}

// round 3
// speedup vs baseline: 6.1805x; 2.0766x over previous
#include <cuda_runtime.h>
#include <cuda_bf16.h>
#include <math.h>

// Problem constants
#define cB   8
#define cS   512
#define cH   768
#define cL   12
#define cNH  12
#define cDH  64
#define cDFF 3072
#define cNL  19
#define cM   (cB * cS)   // 4096 rows

typedef __nv_bfloat16 bf16;
typedef __nv_bfloat162 bf162;

// ---------------------------------------------------------------------------
// Scratch (static device globals; no allocations anywhere)
// ---------------------------------------------------------------------------
__device__ float g_x   [cM * cH];          // fp32 residual stream
__device__ float g_tmp [cM * cH];
__device__ bf16  g_xh  [cM * cH];          // bf16 copy of LN output (GEMM A)
__device__ bf16  g_qh  [cM * cH];
__device__ bf16  g_kh  [cM * cH];
__device__ bf16  g_vh  [cM * cH];
__device__ bf16  g_ctxh[cM * cH];
__device__ bf16  g_ffnh[cM * cDFF];
__device__ float g_logits[cM * cNL];
__device__ float g_pb  [cB];
__device__ float g_maskb[cB * cS];

// bf16 weights (converted each launch)
__device__ bf16 g_wq_h[cL * cH * cH];
__device__ bf16 g_wk_h[cL * cH * cH];
__device__ bf16 g_wv_h[cL * cH * cH];
__device__ bf16 g_wo_h[cL * cH * cH];
__device__ bf16 g_w1_h[cL * cH * cDFF];
__device__ bf16 g_w2_h[cL * cDFF * cH];

// ---------------------------------------------------------------------------
// Helpers
// ---------------------------------------------------------------------------
__device__ __forceinline__ float gelu_tanh(float x) {
    float c = 0.7978845608028654f * (x + 0.044715f * x * x * x);
    return 0.5f * x * (1.0f + tanhf(c));
}

__device__ __forceinline__ void cp16(void* smem, const void* gmem) {
    unsigned a = (unsigned)__cvta_generic_to_shared(smem);
    asm volatile("cp.async.cg.shared.global [%0], [%1], 16;\n" :: "r"(a), "l"(gmem));
}
#define CP_COMMIT asm volatile("cp.async.commit_group;\n" ::: "memory")

__device__ __forceinline__ void ldsm4(unsigned& r0, unsigned& r1, unsigned& r2, unsigned& r3,
                                      const void* p) {
    unsigned a = (unsigned)__cvta_generic_to_shared(p);
    asm volatile("ldmatrix.sync.aligned.m8n8.x4.shared.b16 {%0,%1,%2,%3},[%4];\n"
                 : "=r"(r0), "=r"(r1), "=r"(r2), "=r"(r3) : "r"(a));
}
__device__ __forceinline__ void ldsm4t(unsigned& r0, unsigned& r1, unsigned& r2, unsigned& r3,
                                       const void* p) {
    unsigned a = (unsigned)__cvta_generic_to_shared(p);
    asm volatile("ldmatrix.sync.aligned.m8n8.x4.trans.shared.b16 {%0,%1,%2,%3},[%4];\n"
                 : "=r"(r0), "=r"(r1), "=r"(r2), "=r"(r3) : "r"(a));
}

// m16n8k16 BF16 mma, fp32 accumulate
__device__ __forceinline__ void mma16(float* c, const unsigned* a, unsigned b0, unsigned b1) {
    asm volatile(
        "mma.sync.aligned.m16n8k16.row.col.f32.bf16.bf16.f32 "
        "{%0,%1,%2,%3},{%4,%5,%6,%7},{%8,%9},{%0,%1,%2,%3};\n"
        : "+f"(c[0]), "+f"(c[1]), "+f"(c[2]), "+f"(c[3])
        : "r"(a[0]), "r"(a[1]), "r"(a[2]), "r"(a[3]), "r"(b0), "r"(b1));
}

__device__ __forceinline__ unsigned packbf(float x, float y) {
    bf162 h = __floats2bfloat162_rn(x, y);
    return *(unsigned*)&h;
}

// ---------------------------------------------------------------------------
// fp32 -> bf16 conversion (grid-stride)
// ---------------------------------------------------------------------------
__global__ void conv_k(const float* __restrict__ s, bf16* __restrict__ d, int n) {
    int i = blockIdx.x * blockDim.x + threadIdx.x;
    int stride = gridDim.x * blockDim.x;
    for (; i < n; i += stride) d[i] = __float2bfloat16(s[i]);
}

__global__ void maskb_k(const int* __restrict__ amask, float* __restrict__ mb) {
    int i = blockIdx.x * blockDim.x + threadIdx.x;
    if (i < cB * cS) mb[i] = (1.0f - (float)amask[i]) * -1e9f;
}

// ---------------------------------------------------------------------------
// BF16 tensor-core GEMM: C[M,N] = A[M,K] @ B[K,N] (+bias, epilogues)
// 128x128 tile, BK=32, 256 threads (8 warps 2x4), warp 64x32, 3-stage cp.async.
// EPI: 0 = bias -> bf16 out, 1 = bias+gelu -> bf16 out, 2 = bias+fp32resid -> fp32 out
// ---------------------------------------------------------------------------
template <int EPI>
__device__ __forceinline__ void gemm_body(
    const bf16* __restrict__ A, const bf16* __restrict__ Bm,
    const float* __restrict__ bias, const float* __restrict__ resid,
    void* __restrict__ Cv, int N, int K, int rowBase, int colBase)
{
    __shared__ bf16 As[3][128][40];    // stride 40 halfs -> conflict-free ldmatrix
    __shared__ bf16 Bs[3][32][136];    // stride 136 halfs -> conflict-free trans ldmatrix

    const int tid  = threadIdx.x;
    const int lane = tid & 31;
    const int warp = tid >> 5;
    const int wm   = warp >> 2;
    const int wn   = warp & 3;

    float acc[4][4][4];
    #pragma unroll
    for (int i = 0; i < 4; i++)
        #pragma unroll
        for (int j = 0; j < 4; j++)
            #pragma unroll
            for (int r = 0; r < 4; r++) acc[i][j][r] = 0.0f;

    auto issue = [&](int s, int kt) {
        const int k0 = kt * 32;
        #pragma unroll
        for (int j = 0; j < 2; j++) {
            int idx = tid + j * 256;
            int r = idx >> 2, seg = idx & 3;
            cp16(&As[s][r][seg * 8], A + (size_t)(rowBase + r) * K + k0 + seg * 8);
        }
        #pragma unroll
        for (int j = 0; j < 2; j++) {
            int idx = tid + j * 256;
            int kk = idx >> 4, seg = idx & 15;
            cp16(&Bs[s][kk][seg * 8], Bm + (size_t)(k0 + kk) * N + colBase + seg * 8);
        }
    };

    const int nK = K / 32;
    issue(0, 0); CP_COMMIT;
    issue(1, 1); CP_COMMIT;

    for (int kt = 0; kt < nK; kt++) {
        asm volatile("cp.async.wait_group 1;\n" ::: "memory");
        __syncthreads();
        if (kt + 2 < nK) issue((kt + 2) % 3, kt + 2);
        CP_COMMIT;

        const int s = kt % 3;
        #pragma unroll
        for (int ks = 0; ks < 2; ks++) {
            unsigned af[4][4];
            #pragma unroll
            for (int mt = 0; mt < 4; mt++)
                ldsm4(af[mt][0], af[mt][1], af[mt][2], af[mt][3],
                      &As[s][wm * 64 + mt * 16 + (lane & 15)][ks * 16 + (lane >> 4) * 8]);
            #pragma unroll
            for (int p = 0; p < 2; p++) {
                unsigned r0, r1, r2, r3;
                int krow = ks * 16 + (lane & 7) + ((lane >> 3) & 1) * 8;
                int ncol = wn * 32 + p * 16 + (lane >> 4) * 8;
                ldsm4t(r0, r1, r2, r3, &Bs[s][krow][ncol]);
                #pragma unroll
                for (int mt = 0; mt < 4; mt++) {
                    mma16(acc[mt][2 * p],     af[mt], r0, r1);
                    mma16(acc[mt][2 * p + 1], af[mt], r2, r3);
                }
            }
        }
    }

    // Epilogue
    #pragma unroll
    for (int mt = 0; mt < 4; mt++) {
        #pragma unroll
        for (int nt = 0; nt < 4; nt++) {
            int col = colBase + wn * 32 + nt * 8 + 2 * (lane & 3);
            float2 bv = *(const float2*)&bias[col];
            #pragma unroll
            for (int h = 0; h < 2; h++) {
                int row = rowBase + wm * 64 + mt * 16 + (lane >> 2) + h * 8;
                float ox = acc[mt][nt][h * 2 + 0] + bv.x;
                float oy = acc[mt][nt][h * 2 + 1] + bv.y;
                if (EPI == 0) {
                    bf162 o = __floats2bfloat162_rn(ox, oy);
                    *(bf162*)((bf16*)Cv + (size_t)row * N + col) = o;
                } else if (EPI == 1) {
                    bf162 o = __floats2bfloat162_rn(gelu_tanh(ox), gelu_tanh(oy));
                    *(bf162*)((bf16*)Cv + (size_t)row * N + col) = o;
                } else {
                    float2 rv = *(const float2*)&resid[(size_t)row * N + col];
                    *(float2*)((float*)Cv + (size_t)row * N + col) =
                        make_float2(ox + rv.x, oy + rv.y);
                }
            }
        }
    }
}

template <int EPI>
__global__ __launch_bounds__(256)
void gemm_k(const bf16* __restrict__ A, const bf16* __restrict__ Bm,
            const float* __restrict__ bias, const float* __restrict__ resid,
            void* __restrict__ C, int N, int K)
{
    gemm_body<EPI>(A, Bm, bias, resid, C, N, K, blockIdx.y * 128, blockIdx.x * 128);
}

// Fused QKV via grid.z
__global__ __launch_bounds__(256)
void qkv_k(const bf16* __restrict__ x,
           const bf16* __restrict__ Wq, const bf16* __restrict__ Wk, const bf16* __restrict__ Wv,
           const float* __restrict__ bq, const float* __restrict__ bk, const float* __restrict__ bv,
           bf16* __restrict__ q, bf16* __restrict__ k, bf16* __restrict__ v,
           int N, int K)
{
    const bf16* W; const float* bb; bf16* o;
    if (blockIdx.z == 0)      { W = Wq; bb = bq; o = q; }
    else if (blockIdx.z == 1) { W = Wk; bb = bk; o = k; }
    else                      { W = Wv; bb = bv; o = v; }
    gemm_body<0>(x, W, bb, nullptr, o, N, K, blockIdx.y * 128, blockIdx.x * 128);
}

// ---------------------------------------------------------------------------
// Flash attention: one (b,h), 128 q-rows per block, loop k-tiles of 64.
// 256 threads / 8 warps, each warp 16 q-rows. bf16 mma, fp32 online softmax.
// ---------------------------------------------------------------------------
__global__ __launch_bounds__(256)
void flash_k(const bf16* __restrict__ q, const bf16* __restrict__ k,
             const bf16* __restrict__ v, const float* __restrict__ maskb,
             bf16* __restrict__ ctx)
{
    const int bh = blockIdx.y, b = bh / cNH, h = bh % cNH;
    const int qBase = blockIdx.x * 128;

    __shared__ bf16 Qs[128][72];
    __shared__ bf16 Ks[2][64][72];
    __shared__ bf16 Vs[2][64][72];
    __shared__ float mb[cS];

    const int tid = threadIdx.x, lane = tid & 31, warp = tid >> 5;

    // Q load (part of cp group 0)
    #pragma unroll
    for (int j = 0; j < 4; j++) {
        int idx = tid + j * 256;
        int r = idx >> 3, seg = idx & 7;
        cp16(&Qs[r][seg * 8], q + (size_t)(b * cS + qBase + r) * cH + h * cDH + seg * 8);
    }
    auto issueKV = [&](int s, int kt) {
        #pragma unroll
        for (int j = 0; j < 2; j++) {
            int idx = tid + j * 256;
            int r = idx >> 3, seg = idx & 7;
            size_t off = (size_t)(b * cS + kt * 64 + r) * cH + h * cDH + seg * 8;
            cp16(&Ks[s][r][seg * 8], k + off);
            cp16(&Vs[s][r][seg * 8], v + off);
        }
    };
    issueKV(0, 0); CP_COMMIT;
    for (int i = tid; i < cS; i += 256) mb[i] = maskb[b * cS + i];

    float accO[8][4];
    #pragma unroll
    for (int i = 0; i < 8; i++)
        #pragma unroll
        for (int j = 0; j < 4; j++) accO[i][j] = 0.0f;
    float mrow0 = -1e30f, mrow1 = -1e30f, lrow0 = 0.0f, lrow1 = 0.0f;
    unsigned qf[4][4];

    const int mr = lane & 7;

    for (int kt = 0; kt < cS / 64; kt++) {
        asm volatile("cp.async.wait_group 0;\n" ::: "memory");
        __syncthreads();
        if (kt + 1 < cS / 64) { issueKV((kt + 1) & 1, kt + 1); CP_COMMIT; }
        if (kt == 0) {
            #pragma unroll
            for (int ks = 0; ks < 4; ks++)
                ldsm4(qf[ks][0], qf[ks][1], qf[ks][2], qf[ks][3],
                      &Qs[warp * 16 + (lane & 15)][ks * 16 + (lane >> 4) * 8]);
        }
        const int s = kt & 1;

        // S = Q @ K^T   (warp: 16 q x 64 keys)
        float p[8][4];
        #pragma unroll
        for (int i = 0; i < 8; i++)
            #pragma unroll
            for (int j = 0; j < 4; j++) p[i][j] = 0.0f;

        #pragma unroll
        for (int ks = 0; ks < 4; ks++) {
            const int d0 = ks * 16;
            #pragma unroll
            for (int p2 = 0; p2 < 4; p2++) {
                unsigned r0, r1, r2, r3;
                int keyrow = p2 * 16 + mr + (lane >> 4) * 8;
                int dcol   = d0 + ((lane >> 3) & 1) * 8;
                ldsm4(r0, r1, r2, r3, &Ks[s][keyrow][dcol]);
                mma16(p[2 * p2],     qf[ks], r0, r1);
                mma16(p[2 * p2 + 1], qf[ks], r2, r3);
            }
        }

        // scale + bias + online softmax
        const float scale = 0.125f;
        float mt0 = -1e30f, mt1 = -1e30f;
        #pragma unroll
        for (int nt = 0; nt < 8; nt++) {
            int col = kt * 64 + nt * 8 + 2 * (lane & 3);
            float b0v = mb[col], b1v = mb[col + 1];
            p[nt][0] = p[nt][0] * scale + b0v;
            p[nt][1] = p[nt][1] * scale + b1v;
            p[nt][2] = p[nt][2] * scale + b0v;
            p[nt][3] = p[nt][3] * scale + b1v;
            mt0 = fmaxf(mt0, fmaxf(p[nt][0], p[nt][1]));
            mt1 = fmaxf(mt1, fmaxf(p[nt][2], p[nt][3]));
        }
        mt0 = fmaxf(mt0, __shfl_xor_sync(0xffffffffu, mt0, 1));
        mt0 = fmaxf(mt0, __shfl_xor_sync(0xffffffffu, mt0, 2));
        mt1 = fmaxf(mt1, __shfl_xor_sync(0xffffffffu, mt1, 1));
        mt1 = fmaxf(mt1, __shfl_xor_sync(0xffffffffu, mt1, 2));

        float mn0 = fmaxf(mrow0, mt0), mn1 = fmaxf(mrow1, mt1);
        float f0 = __expf(mrow0 - mn0), f1 = __expf(mrow1 - mn1);
        float sum0 = 0.0f, sum1 = 0.0f;
        #pragma unroll
        for (int nt = 0; nt < 8; nt++) {
            p[nt][0] = __expf(p[nt][0] - mn0);
            p[nt][1] = __expf(p[nt][1] - mn0);
            p[nt][2] = __expf(p[nt][2] - mn1);
            p[nt][3] = __expf(p[nt][3] - mn1);
            sum0 += p[nt][0] + p[nt][1];
            sum1 += p[nt][2] + p[nt][3];
        }
        sum0 += __shfl_xor_sync(0xffffffffu, sum0, 1);
        sum0 += __shfl_xor_sync(0xffffffffu, sum0, 2);
        sum1 += __shfl_xor_sync(0xffffffffu, sum1, 1);
        sum1 += __shfl_xor_sync(0xffffffffu, sum1, 2);
        lrow0 = lrow0 * f0 + sum0;
        lrow1 = lrow1 * f1 + sum1;
        mrow0 = mn0; mrow1 = mn1;
        #pragma unroll
        for (int dt = 0; dt < 8; dt++) {
            accO[dt][0] *= f0; accO[dt][1] *= f0;
            accO[dt][2] *= f1; accO[dt][3] *= f1;
        }

        // pack P to bf16 A-fragments
        unsigned pf[4][4];
        #pragma unroll
        for (int j = 0; j < 4; j++) {
            pf[j][0] = packbf(p[2 * j][0],     p[2 * j][1]);
            pf[j][1] = packbf(p[2 * j][2],     p[2 * j][3]);
            pf[j][2] = packbf(p[2 * j + 1][0], p[2 * j + 1][1]);
            pf[j][3] = packbf(p[2 * j + 1][2], p[2 * j + 1][3]);
        }

        // O += P @ V
        #pragma unroll
        for (int j = 0; j < 4; j++) {
            const int kk = j * 16;
            #pragma unroll
            for (int dp = 0; dp < 4; dp++) {
                unsigned r0, r1, r2, r3;
                int krow = kk + mr + ((lane >> 3) & 1) * 8;
                int dcol = dp * 16 + (lane >> 4) * 8;
                ldsm4t(r0, r1, r2, r3, &Vs[s][krow][dcol]);
                mma16(accO[2 * dp],     pf[j], r0, r1);
                mma16(accO[2 * dp + 1], pf[j], r2, r3);
            }
        }
    }

    // normalize + write ctx (bf16, [b,s][h*64+d])
    float i0 = 1.0f / lrow0, i1 = 1.0f / lrow1;
    int r0 = qBase + warp * 16 + (lane >> 2);
    #pragma unroll
    for (int dt = 0; dt < 8; dt++) {
        int d = dt * 8 + 2 * (lane & 3);
        bf162 o0 = __floats2bfloat162_rn(accO[dt][0] * i0, accO[dt][1] * i0);
        *(bf162*)&ctx[(size_t)(b * cS + r0) * cH + h * cDH + d] = o0;
        bf162 o1 = __floats2bfloat162_rn(accO[dt][2] * i1, accO[dt][3] * i1);
        *(bf162*)&ctx[(size_t)(b * cS + r0 + 8) * cH + h * cDH + d] = o1;
    }
}

// ---------------------------------------------------------------------------
// LayerNorm over last dim (768): fp32 out + bf16 out. grid = B*S, 256 threads.
// ---------------------------------------------------------------------------
__global__ __launch_bounds__(256)
void ln_k(const float* __restrict__ in, const float* __restrict__ s,
          const float* __restrict__ bp, float* __restrict__ outf,
          bf16* __restrict__ outh)
{
    __shared__ float red[256];
    const float* xr = in + (size_t)blockIdx.x * cH;
    const int tid = threadIdx.x;

    float v0 = xr[tid], v1 = xr[tid + 256], v2 = xr[tid + 512];
    red[tid] = v0 + v1 + v2;
    __syncthreads();
    for (int s2 = 128; s2 > 0; s2 >>= 1) {
        if (tid < s2) red[tid] += red[tid + s2];
        __syncthreads();
    }
    float m = red[0] * (1.0f / (float)cH);
    __syncthreads();

    float d0 = v0 - m, d1 = v1 - m, d2 = v2 - m;
    red[tid] = d0 * d0 + d1 * d1 + d2 * d2;
    __syncthreads();
    for (int s2 = 128; s2 > 0; s2 >>= 1) {
        if (tid < s2) red[tid] += red[tid + s2];
        __syncthreads();
    }
    float var = red[0] * (1.0f / (float)cH);
    float r = rsqrtf(var + 1e-12f);

    float o0 = d0 * r * s[tid]       + bp[tid];
    float o1 = d1 * r * s[tid + 256] + bp[tid + 256];
    float o2 = d2 * r * s[tid + 512] + bp[tid + 512];
    float* orow = outf + (size_t)blockIdx.x * cH;
    bf16*  hrow = outh + (size_t)blockIdx.x * cH;
    orow[tid] = o0; orow[tid + 256] = o1; orow[tid + 512] = o2;
    hrow[tid]       = __float2bfloat16(o0);
    hrow[tid + 256] = __float2bfloat16(o1);
    hrow[tid + 512] = __float2bfloat16(o2);
}

// ---------------------------------------------------------------------------
// Embedding
// ---------------------------------------------------------------------------
__global__ void embed_k(const int* __restrict__ ids, const float* __restrict__ te,
                        const float* __restrict__ pe, float* __restrict__ out)
{
    const int bs = blockIdx.x;
    const int s2 = bs % cS;
    const int id = ids[bs];
    for (int h = threadIdx.x; h < cH; h += blockDim.x)
        out[(size_t)bs * cH + h] = te[(size_t)id * cH + h] + pe[s2 * cH + h];
}

// ---------------------------------------------------------------------------
// Classifier (N=19), fp32
// ---------------------------------------------------------------------------
__global__ __launch_bounds__(128)
void cls_k(const float* __restrict__ x, const float* __restrict__ W,
           const float* __restrict__ bias, float* __restrict__ logits)
{
    __shared__ float xs[cH];
    const int row = blockIdx.x;
    const int tid = threadIdx.x;
    for (int h = tid; h < cH; h += 128) xs[h] = x[(size_t)row * cH + h];
    __syncthreads();

    const int warp = tid >> 5, lane = tid & 31;
    for (int j = warp; j < cNL; j += 4) {
        float sum = 0.0f;
        for (int k2 = lane; k2 < cH; k2 += 32)
            sum = fmaf(xs[k2], W[k2 * cNL + j], sum);
        #pragma unroll
        for (int o = 16; o > 0; o >>= 1)
            sum += __shfl_down_sync(0xffffffffu, sum, o);
        if (lane == 0) logits[(size_t)row * cNL + j] = sum + bias[j];
    }
}

// ---------------------------------------------------------------------------
// CRF
// ---------------------------------------------------------------------------
__global__ __launch_bounds__(32)
void crf_k(const float* __restrict__ logits, const int* __restrict__ labels,
           const int* __restrict__ amask, const float* __restrict__ startT,
           const float* __restrict__ endT, const float* __restrict__ trans,
           float* __restrict__ pb)
{
    const int b = blockIdx.x;
    const int j = threadIdx.x;

    __shared__ float tT[cNL][cNL + 1];
    __shared__ float alpha[cNL];
    __shared__ float num_s;

    for (int idx = j; idx < cNL * cNL; idx += 32) {
        int i = idx / cNL, jj = idx % cNL;
        tT[jj][i] = trans[idx];
    }

    const int* lab = labels + b * cS;
    const int* mk  = amask + b * cS;
    const float* lg = logits + (size_t)b * cS * cNL;

    if (j == 0) {
        float num = startT[lab[0]] + lg[lab[0]];
        float msum = (float)mk[0];
        for (int t = 1; t < cS; t++) {
            float mf = (float)mk[t];
            num += (trans[lab[t - 1] * cNL + lab[t]] + lg[t * cNL + lab[t]]) * mf;
            msum += mf;
        }
        int last = (int)msum - 1;
        num += endT[lab[last]];
        num_s = num;
    }
    __syncthreads();

    if (j < cNL) alpha[j] = startT[j] + lg[j];
    __syncthreads();

    for (int t = 1; t < cS; t++) {
        float nv = 0.0f;
        if (j < cNL) {
            float m = -1e30f;
            #pragma unroll
            for (int i = 0; i < cNL; i++) m = fmaxf(m, alpha[i] + tT[j][i]);
            float ss = 0.0f;
            #pragma unroll
            for (int i = 0; i < cNL; i++) ss += expf(alpha[i] + tT[j][i] - m);
            float nxt = m + logf(ss) + lg[t * cNL + j];
            nv = ((float)mk[t] > 0.0f) ? nxt : alpha[j];
        }
        __syncthreads();
        if (j < cNL) alpha[j] = nv;
        __syncthreads();
    }

    if (j == 0) {
        float m = -1e30f;
        #pragma unroll
        for (int jj = 0; jj < cNL; jj++) m = fmaxf(m, alpha[jj] + endT[jj]);
        float ss = 0.0f;
        #pragma unroll
        for (int jj = 0; jj < cNL; jj++) ss += expf(alpha[jj] + endT[jj] - m);
        pb[b] = (m + logf(ss)) - num_s;
    }
}

__global__ void final_k(const float* __restrict__ pb, float* __restrict__ out)
{
    float s2 = 0.0f;
    for (int b2 = 0; b2 < cB; b2++) s2 += pb[b2];
    out[0] = s2;
}

// ---------------------------------------------------------------------------
// Launch
// ---------------------------------------------------------------------------
extern "C" void kernel_launch(void* const* d_in, const int* in_sizes, int n_in,
                              void* d_out, int out_size)
{
    const int*   ids       = (const int*)d_in[0];
    const int*   amask     = (const int*)d_in[1];
    const int*   labels    = (const int*)d_in[2];
    const float* token_emb = (const float*)d_in[3];
    const float* pos_emb   = (const float*)d_in[4];
    const float* ln_emb_s  = (const float*)d_in[5];
    const float* ln_emb_b  = (const float*)d_in[6];
    const float* Wq        = (const float*)d_in[7];
    const float* bq        = (const float*)d_in[8];
    const float* Wk        = (const float*)d_in[9];
    const float* bk        = (const float*)d_in[10];
    const float* Wv        = (const float*)d_in[11];
    const float* bv        = (const float*)d_in[12];
    const float* Wo        = (const float*)d_in[13];
    const float* bo        = (const float*)d_in[14];
    const float* ln1_s     = (const float*)d_in[15];
    const float* ln1_b     = (const float*)d_in[16];
    const float* W1        = (const float*)d_in[17];
    const float* b1        = (const float*)d_in[18];
    const float* W2        = (const float*)d_in[19];
    const float* b2        = (const float*)d_in[20];
    const float* ln2_s     = (const float*)d_in[21];
    const float* ln2_b     = (const float*)d_in[22];
    const float* cls_W     = (const float*)d_in[23];
    const float* cls_b     = (const float*)d_in[24];
    const float* startT    = (const float*)d_in[25];
    const float* endT      = (const float*)d_in[26];
    const float* trans     = (const float*)d_in[27];

    float *px, *ptmp, *plogits, *ppb, *pmaskb;
    bf16 *pxh, *pqh, *pkh, *pvh, *pctxh, *pffnh;
    bf16 *pwq, *pwk, *pwv, *pwo, *pw1, *pw2;
    cudaGetSymbolAddress((void**)&px, g_x);
    cudaGetSymbolAddress((void**)&ptmp, g_tmp);
    cudaGetSymbolAddress((void**)&pxh, g_xh);
    cudaGetSymbolAddress((void**)&pqh, g_qh);
    cudaGetSymbolAddress((void**)&pkh, g_kh);
    cudaGetSymbolAddress((void**)&pvh, g_vh);
    cudaGetSymbolAddress((void**)&pctxh, g_ctxh);
    cudaGetSymbolAddress((void**)&pffnh, g_ffnh);
    cudaGetSymbolAddress((void**)&plogits, g_logits);
    cudaGetSymbolAddress((void**)&ppb, g_pb);
    cudaGetSymbolAddress((void**)&pmaskb, g_maskb);
    cudaGetSymbolAddress((void**)&pwq, g_wq_h);
    cudaGetSymbolAddress((void**)&pwk, g_wk_h);
    cudaGetSymbolAddress((void**)&pwv, g_wv_h);
    cudaGetSymbolAddress((void**)&pwo, g_wo_h);
    cudaGetSymbolAddress((void**)&pw1, g_w1_h);
    cudaGetSymbolAddress((void**)&pw2, g_w2_h);

    // Weight conversion (once per launch)
    const int nHH = cL * cH * cH;
    const int nHF = cL * cH * cDFF;
    conv_k<<<2048, 256>>>(Wq, pwq, nHH);
    conv_k<<<2048, 256>>>(Wk, pwk, nHH);
    conv_k<<<2048, 256>>>(Wv, pwv, nHH);
    conv_k<<<2048, 256>>>(Wo, pwo, nHH);
    conv_k<<<4096, 256>>>(W1, pw1, nHF);
    conv_k<<<4096, 256>>>(W2, pw2, nHF);
    maskb_k<<<16, 256>>>(amask, pmaskb);

    embed_k<<<cM, 256>>>(ids, token_emb, pos_emb, ptmp);
    ln_k<<<cM, 256>>>(ptmp, ln_emb_s, ln_emb_b, px, pxh);

    const dim3 gQKV(cH / 128, cM / 128, 3);   // (6, 32, 3)
    const dim3 gHH (cH / 128, cM / 128);      // (6, 32)
    const dim3 gHF (cDFF / 128, cM / 128);    // (24, 32)
    const dim3 gFl (cS / 128, cB * cNH);      // (4, 96)

    for (int l = 0; l < cL; l++) {
        qkv_k<<<gQKV, 256>>>(pxh, pwq + (size_t)l * cH * cH, pwk + (size_t)l * cH * cH,
                             pwv + (size_t)l * cH * cH,
                             bq + l * cH, bk + l * cH, bv + l * cH,
                             pqh, pkh, pvh, cH, cH);

        flash_k<<<gFl, 256>>>(pqh, pkh, pvh, pmaskb, pctxh);

        gemm_k<2><<<gHH, 256>>>(pctxh, pwo + (size_t)l * cH * cH, bo + l * cH, px,
                                ptmp, cH, cH);
        ln_k<<<cM, 256>>>(ptmp, ln1_s + l * cH, ln1_b + l * cH, px, pxh);

        gemm_k<1><<<gHF, 256>>>(pxh, pw1 + (size_t)l * cH * cDFF, b1 + l * cDFF, nullptr,
                                pffnh, cDFF, cH);
        gemm_k<2><<<gHH, 256>>>(pffnh, pw2 + (size_t)l * cDFF * cH, b2 + l * cH, px,
                                ptmp, cH, cDFF);
        ln_k<<<cM, 256>>>(ptmp, ln2_s + l * cH, ln2_b + l * cH, px, pxh);
    }

    cls_k<<<cM, 128>>>(px, cls_W, cls_b, plogits);
    crf_k<<<cB, 32>>>(plogits, labels, amask, startT, endT, trans, ppb);
    final_k<<<1, 1>>>(ppb, (float*)d_out);
}

// round 5
// speedup vs baseline: 6.8162x; 1.1029x over previous
#include <cuda_runtime.h>
#include <cuda_bf16.h>
#include <math.h>

// Problem constants
#define cB   8
#define cS   512
#define cH   768
#define cL   12
#define cNH  12
#define cDH  64
#define cDFF 3072
#define cNL  19
#define cM   (cB * cS)   // 4096 rows

typedef __nv_bfloat16 bf16;
typedef __nv_bfloat162 bf162;

// ---------------------------------------------------------------------------
// Scratch (static device globals; no allocations anywhere)
// ---------------------------------------------------------------------------
__device__ float g_x   [cM * cH];          // fp32 residual stream
__device__ float g_tmp [cM * cH];
__device__ bf16  g_xh  [cM * cH];          // bf16 copy of LN output (GEMM A)
__device__ bf16  g_qh  [cM * cH];
__device__ bf16  g_kh  [cM * cH];
__device__ bf16  g_vh  [cM * cH];
__device__ bf16  g_ctxh[cM * cH];
__device__ bf16  g_ffnh[cM * cDFF];
__device__ float g_logits[cM * cNL];
__device__ float g_pb  [cB];
__device__ float g_maskb[cB * cS];

// bf16 weights (converted each launch)
__device__ bf16 g_wq_h[cL * cH * cH];
__device__ bf16 g_wk_h[cL * cH * cH];
__device__ bf16 g_wv_h[cL * cH * cH];
__device__ bf16 g_wo_h[cL * cH * cH];
__device__ bf16 g_w1_h[cL * cH * cDFF];
__device__ bf16 g_w2_h[cL * cDFF * cH];

// ---------------------------------------------------------------------------
// Helpers
// ---------------------------------------------------------------------------
__device__ __forceinline__ float gelu_tanh(float x) {
    float c = 0.7978845608028654f * (x + 0.044715f * x * x * x);
    return 0.5f * x * (1.0f + tanhf(c));
}

__device__ __forceinline__ void cp16(void* smem, const void* gmem) {
    unsigned a = (unsigned)__cvta_generic_to_shared(smem);
    asm volatile("cp.async.cg.shared.global [%0], [%1], 16;\n" :: "r"(a), "l"(gmem));
}
#define CP_COMMIT asm volatile("cp.async.commit_group;\n" ::: "memory")

__device__ __forceinline__ void ldsm4(unsigned& r0, unsigned& r1, unsigned& r2, unsigned& r3,
                                      const void* p) {
    unsigned a = (unsigned)__cvta_generic_to_shared(p);
    asm volatile("ldmatrix.sync.aligned.m8n8.x4.shared.b16 {%0,%1,%2,%3},[%4];\n"
                 : "=r"(r0), "=r"(r1), "=r"(r2), "=r"(r3) : "r"(a));
}
__device__ __forceinline__ void ldsm4t(unsigned& r0, unsigned& r1, unsigned& r2, unsigned& r3,
                                       const void* p) {
    unsigned a = (unsigned)__cvta_generic_to_shared(p);
    asm volatile("ldmatrix.sync.aligned.m8n8.x4.trans.shared.b16 {%0,%1,%2,%3},[%4];\n"
                 : "=r"(r0), "=r"(r1), "=r"(r2), "=r"(r3) : "r"(a));
}

// m16n8k16 BF16 mma, fp32 accumulate
__device__ __forceinline__ void mma16(float* c, const unsigned* a, unsigned b0, unsigned b1) {
    asm volatile(
        "mma.sync.aligned.m16n8k16.row.col.f32.bf16.bf16.f32 "
        "{%0,%1,%2,%3},{%4,%5,%6,%7},{%8,%9},{%0,%1,%2,%3};\n"
        : "+f"(c[0]), "+f"(c[1]), "+f"(c[2]), "+f"(c[3])
        : "r"(a[0]), "r"(a[1]), "r"(a[2]), "r"(a[3]), "r"(b0), "r"(b1));
}

__device__ __forceinline__ unsigned packbf(float x, float y) {
    bf162 h = __floats2bfloat162_rn(x, y);
    return *(unsigned*)&h;
}

// ---------------------------------------------------------------------------
// fp32 -> bf16 conversion, vectorized (4 elems/thread/iter)
// ---------------------------------------------------------------------------
__global__ __launch_bounds__(256)
void conv_k(const float4* __restrict__ s, uint2* __restrict__ d, int n4) {
    int i = blockIdx.x * blockDim.x + threadIdx.x;
    int stride = gridDim.x * blockDim.x;
    for (; i < n4; i += stride) {
        float4 v = s[i];
        uint2 o;
        o.x = packbf(v.x, v.y);
        o.y = packbf(v.z, v.w);
        d[i] = o;
    }
}

__global__ void maskb_k(const int* __restrict__ amask, float* __restrict__ mb) {
    int i = blockIdx.x * blockDim.x + threadIdx.x;
    if (i < cB * cS) mb[i] = (1.0f - (float)amask[i]) * -1e9f;
}

// ---------------------------------------------------------------------------
// BF16 tensor-core GEMM: C[M,N] = A[M,K] @ B[K,N] (+bias, epilogues)
// 128x128 tile, BK=32, 256 threads (8 warps 2x4), warp 64x32, 3-stage cp.async.
// EPI: 0 = bias -> bf16 out, 1 = bias+gelu -> bf16 out, 2 = bias+fp32resid -> fp32 out
// ---------------------------------------------------------------------------
template <int EPI>
__device__ __forceinline__ void gemm_body(
    const bf16* __restrict__ A, const bf16* __restrict__ Bm,
    const float* __restrict__ bias, const float* __restrict__ resid,
    void* __restrict__ Cv, int N, int K, int rowBase, int colBase)
{
    __shared__ bf16 As[3][128][40];    // stride 40 halfs -> conflict-free ldmatrix
    __shared__ bf16 Bs[3][32][136];    // stride 136 halfs -> conflict-free trans ldmatrix

    const int tid  = threadIdx.x;
    const int lane = tid & 31;
    const int warp = tid >> 5;
    const int wm   = warp >> 2;
    const int wn   = warp & 3;

    float acc[4][4][4];
    #pragma unroll
    for (int i = 0; i < 4; i++)
        #pragma unroll
        for (int j = 0; j < 4; j++)
            #pragma unroll
            for (int r = 0; r < 4; r++) acc[i][j][r] = 0.0f;

    auto issue = [&](int s, int kt) {
        const int k0 = kt * 32;
        #pragma unroll
        for (int j = 0; j < 2; j++) {
            int idx = tid + j * 256;
            int r = idx >> 2, seg = idx & 3;
            cp16(&As[s][r][seg * 8], A + (size_t)(rowBase + r) * K + k0 + seg * 8);
        }
        #pragma unroll
        for (int j = 0; j < 2; j++) {
            int idx = tid + j * 256;
            int kk = idx >> 4, seg = idx & 15;
            cp16(&Bs[s][kk][seg * 8], Bm + (size_t)(k0 + kk) * N + colBase + seg * 8);
        }
    };

    const int nK = K / 32;
    issue(0, 0); CP_COMMIT;
    issue(1, 1); CP_COMMIT;

    for (int kt = 0; kt < nK; kt++) {
        asm volatile("cp.async.wait_group 1;\n" ::: "memory");
        __syncthreads();
        if (kt + 2 < nK) issue((kt + 2) % 3, kt + 2);
        CP_COMMIT;

        const int s = kt % 3;
        #pragma unroll
        for (int ks = 0; ks < 2; ks++) {
            unsigned af[4][4];
            #pragma unroll
            for (int mt = 0; mt < 4; mt++)
                ldsm4(af[mt][0], af[mt][1], af[mt][2], af[mt][3],
                      &As[s][wm * 64 + mt * 16 + (lane & 15)][ks * 16 + (lane >> 4) * 8]);
            #pragma unroll
            for (int p = 0; p < 2; p++) {
                unsigned r0, r1, r2, r3;
                int krow = ks * 16 + (lane & 7) + ((lane >> 3) & 1) * 8;
                int ncol = wn * 32 + p * 16 + (lane >> 4) * 8;
                ldsm4t(r0, r1, r2, r3, &Bs[s][krow][ncol]);
                #pragma unroll
                for (int mt = 0; mt < 4; mt++) {
                    mma16(acc[mt][2 * p],     af[mt], r0, r1);
                    mma16(acc[mt][2 * p + 1], af[mt], r2, r3);
                }
            }
        }
    }

    // Epilogue
    #pragma unroll
    for (int mt = 0; mt < 4; mt++) {
        #pragma unroll
        for (int nt = 0; nt < 4; nt++) {
            int col = colBase + wn * 32 + nt * 8 + 2 * (lane & 3);
            float2 bv = *(const float2*)&bias[col];
            #pragma unroll
            for (int h = 0; h < 2; h++) {
                int row = rowBase + wm * 64 + mt * 16 + (lane >> 2) + h * 8;
                float ox = acc[mt][nt][h * 2 + 0] + bv.x;
                float oy = acc[mt][nt][h * 2 + 1] + bv.y;
                if (EPI == 0) {
                    bf162 o = __floats2bfloat162_rn(ox, oy);
                    *(bf162*)((bf16*)Cv + (size_t)row * N + col) = o;
                } else if (EPI == 1) {
                    bf162 o = __floats2bfloat162_rn(gelu_tanh(ox), gelu_tanh(oy));
                    *(bf162*)((bf16*)Cv + (size_t)row * N + col) = o;
                } else {
                    float2 rv = *(const float2*)&resid[(size_t)row * N + col];
                    *(float2*)((float*)Cv + (size_t)row * N + col) =
                        make_float2(ox + rv.x, oy + rv.y);
                }
            }
        }
    }
}

template <int EPI>
__global__ __launch_bounds__(256, 2)
void gemm_k(const bf16* __restrict__ A, const bf16* __restrict__ Bm,
            const float* __restrict__ bias, const float* __restrict__ resid,
            void* __restrict__ C, int N, int K)
{
    gemm_body<EPI>(A, Bm, bias, resid, C, N, K, blockIdx.y * 128, blockIdx.x * 128);
}

// Fused QKV via grid.z
__global__ __launch_bounds__(256, 2)
void qkv_k(const bf16* __restrict__ x,
           const bf16* __restrict__ Wq, const bf16* __restrict__ Wk, const bf16* __restrict__ Wv,
           const float* __restrict__ bq, const float* __restrict__ bk, const float* __restrict__ bv,
           bf16* __restrict__ q, bf16* __restrict__ k, bf16* __restrict__ v,
           int N, int K)
{
    const bf16* W; const float* bb; bf16* o;
    if (blockIdx.z == 0)      { W = Wq; bb = bq; o = q; }
    else if (blockIdx.z == 1) { W = Wk; bb = bk; o = k; }
    else                      { W = Wv; bb = bv; o = v; }
    gemm_body<0>(x, W, bb, nullptr, o, N, K, blockIdx.y * 128, blockIdx.x * 128);
}

// ---------------------------------------------------------------------------
// Flash attention: one (b,h), 128 q-rows per block, loop k-tiles of 64.
// 256 threads / 8 warps, each warp 16 q-rows. bf16 mma, fp32 online softmax.
// ---------------------------------------------------------------------------
__global__ __launch_bounds__(256, 2)
void flash_k(const bf16* __restrict__ q, const bf16* __restrict__ k,
             const bf16* __restrict__ v, const float* __restrict__ maskb,
             bf16* __restrict__ ctx)
{
    const int bh = blockIdx.y, b = bh / cNH, h = bh % cNH;
    const int qBase = blockIdx.x * 128;

    __shared__ bf16 Qs[128][72];
    __shared__ bf16 Ks[2][64][72];
    __shared__ bf16 Vs[2][64][72];
    __shared__ float mb[cS];

    const int tid = threadIdx.x, lane = tid & 31, warp = tid >> 5;

    // Q load (part of cp group 0)
    #pragma unroll
    for (int j = 0; j < 4; j++) {
        int idx = tid + j * 256;
        int r = idx >> 3, seg = idx & 7;
        cp16(&Qs[r][seg * 8], q + (size_t)(b * cS + qBase + r) * cH + h * cDH + seg * 8);
    }
    auto issueKV = [&](int s, int kt) {
        #pragma unroll
        for (int j = 0; j < 2; j++) {
            int idx = tid + j * 256;
            int r = idx >> 3, seg = idx & 7;
            size_t off = (size_t)(b * cS + kt * 64 + r) * cH + h * cDH + seg * 8;
            cp16(&Ks[s][r][seg * 8], k + off);
            cp16(&Vs[s][r][seg * 8], v + off);
        }
    };
    issueKV(0, 0); CP_COMMIT;
    for (int i = tid; i < cS; i += 256) mb[i] = maskb[b * cS + i];

    float accO[8][4];
    #pragma unroll
    for (int i = 0; i < 8; i++)
        #pragma unroll
        for (int j = 0; j < 4; j++) accO[i][j] = 0.0f;
    float mrow0 = -1e30f, mrow1 = -1e30f, lrow0 = 0.0f, lrow1 = 0.0f;
    unsigned qf[4][4];

    const int mr = lane & 7;

    for (int kt = 0; kt < cS / 64; kt++) {
        asm volatile("cp.async.wait_group 0;\n" ::: "memory");
        __syncthreads();
        if (kt + 1 < cS / 64) { issueKV((kt + 1) & 1, kt + 1); CP_COMMIT; }
        if (kt == 0) {
            #pragma unroll
            for (int ks = 0; ks < 4; ks++)
                ldsm4(qf[ks][0], qf[ks][1], qf[ks][2], qf[ks][3],
                      &Qs[warp * 16 + (lane & 15)][ks * 16 + (lane >> 4) * 8]);
        }
        const int s = kt & 1;

        // S = Q @ K^T   (warp: 16 q x 64 keys)
        float p[8][4];
        #pragma unroll
        for (int i = 0; i < 8; i++)
            #pragma unroll
            for (int j = 0; j < 4; j++) p[i][j] = 0.0f;

        #pragma unroll
        for (int ks = 0; ks < 4; ks++) {
            const int d0 = ks * 16;
            #pragma unroll
            for (int p2 = 0; p2 < 4; p2++) {
                unsigned r0, r1, r2, r3;
                int keyrow = p2 * 16 + mr + (lane >> 4) * 8;
                int dcol   = d0 + ((lane >> 3) & 1) * 8;
                ldsm4(r0, r1, r2, r3, &Ks[s][keyrow][dcol]);
                mma16(p[2 * p2],     qf[ks], r0, r1);
                mma16(p[2 * p2 + 1], qf[ks], r2, r3);
            }
        }

        // scale + bias + online softmax
        const float scale = 0.125f;
        float mt0 = -1e30f, mt1 = -1e30f;
        #pragma unroll
        for (int nt = 0; nt < 8; nt++) {
            int col = kt * 64 + nt * 8 + 2 * (lane & 3);
            float b0v = mb[col], b1v = mb[col + 1];
            p[nt][0] = p[nt][0] * scale + b0v;
            p[nt][1] = p[nt][1] * scale + b1v;
            p[nt][2] = p[nt][2] * scale + b0v;
            p[nt][3] = p[nt][3] * scale + b1v;
            mt0 = fmaxf(mt0, fmaxf(p[nt][0], p[nt][1]));
            mt1 = fmaxf(mt1, fmaxf(p[nt][2], p[nt][3]));
        }
        mt0 = fmaxf(mt0, __shfl_xor_sync(0xffffffffu, mt0, 1));
        mt0 = fmaxf(mt0, __shfl_xor_sync(0xffffffffu, mt0, 2));
        mt1 = fmaxf(mt1, __shfl_xor_sync(0xffffffffu, mt1, 1));
        mt1 = fmaxf(mt1, __shfl_xor_sync(0xffffffffu, mt1, 2));

        float mn0 = fmaxf(mrow0, mt0), mn1 = fmaxf(mrow1, mt1);
        float f0 = __expf(mrow0 - mn0), f1 = __expf(mrow1 - mn1);
        float sum0 = 0.0f, sum1 = 0.0f;
        #pragma unroll
        for (int nt = 0; nt < 8; nt++) {
            p[nt][0] = __expf(p[nt][0] - mn0);
            p[nt][1] = __expf(p[nt][1] - mn0);
            p[nt][2] = __expf(p[nt][2] - mn1);
            p[nt][3] = __expf(p[nt][3] - mn1);
            sum0 += p[nt][0] + p[nt][1];
            sum1 += p[nt][2] + p[nt][3];
        }
        sum0 += __shfl_xor_sync(0xffffffffu, sum0, 1);
        sum0 += __shfl_xor_sync(0xffffffffu, sum0, 2);
        sum1 += __shfl_xor_sync(0xffffffffu, sum1, 1);
        sum1 += __shfl_xor_sync(0xffffffffu, sum1, 2);
        lrow0 = lrow0 * f0 + sum0;
        lrow1 = lrow1 * f1 + sum1;
        mrow0 = mn0; mrow1 = mn1;
        #pragma unroll
        for (int dt = 0; dt < 8; dt++) {
            accO[dt][0] *= f0; accO[dt][1] *= f0;
            accO[dt][2] *= f1; accO[dt][3] *= f1;
        }

        // pack P to bf16 A-fragments
        unsigned pf[4][4];
        #pragma unroll
        for (int j = 0; j < 4; j++) {
            pf[j][0] = packbf(p[2 * j][0],     p[2 * j][1]);
            pf[j][1] = packbf(p[2 * j][2],     p[2 * j][3]);
            pf[j][2] = packbf(p[2 * j + 1][0], p[2 * j + 1][1]);
            pf[j][3] = packbf(p[2 * j + 1][2], p[2 * j + 1][3]);
        }

        // O += P @ V
        #pragma unroll
        for (int j = 0; j < 4; j++) {
            const int kk = j * 16;
            #pragma unroll
            for (int dp = 0; dp < 4; dp++) {
                unsigned r0, r1, r2, r3;
                int krow = kk + mr + ((lane >> 3) & 1) * 8;
                int dcol = dp * 16 + (lane >> 4) * 8;
                ldsm4t(r0, r1, r2, r3, &Vs[s][krow][dcol]);
                mma16(accO[2 * dp],     pf[j], r0, r1);
                mma16(accO[2 * dp + 1], pf[j], r2, r3);
            }
        }
    }

    // normalize + write ctx (bf16, [b,s][h*64+d])
    float i0 = 1.0f / lrow0, i1 = 1.0f / lrow1;
    int r0 = qBase + warp * 16 + (lane >> 2);
    #pragma unroll
    for (int dt = 0; dt < 8; dt++) {
        int d = dt * 8 + 2 * (lane & 3);
        bf162 o0 = __floats2bfloat162_rn(accO[dt][0] * i0, accO[dt][1] * i0);
        *(bf162*)&ctx[(size_t)(b * cS + r0) * cH + h * cDH + d] = o0;
        bf162 o1 = __floats2bfloat162_rn(accO[dt][2] * i1, accO[dt][3] * i1);
        *(bf162*)&ctx[(size_t)(b * cS + r0 + 8) * cH + h * cDH + d] = o1;
    }
}

// ---------------------------------------------------------------------------
// LayerNorm core: single pass (sum, sumsq), warp-shuffle reductions, 2 barriers.
// 256 threads per row of 768.
// ---------------------------------------------------------------------------
__device__ __forceinline__ void ln_core(
    float v0, float v1, float v2,
    const float* __restrict__ s, const float* __restrict__ bp,
    float* __restrict__ orow, bf16* __restrict__ hrow, int tid)
{
    __shared__ float2 wred[8];
    const int lane = tid & 31, warp = tid >> 5;

    float2 a = make_float2(v0 + v1 + v2, v0 * v0 + v1 * v1 + v2 * v2);
    #pragma unroll
    for (int o = 16; o > 0; o >>= 1) {
        a.x += __shfl_xor_sync(0xffffffffu, a.x, o);
        a.y += __shfl_xor_sync(0xffffffffu, a.y, o);
    }
    if (lane == 0) wred[warp] = a;
    __syncthreads();
    if (warp == 0) {
        float2 t = (lane < 8) ? wred[lane] : make_float2(0.0f, 0.0f);
        #pragma unroll
        for (int o = 4; o > 0; o >>= 1) {
            t.x += __shfl_xor_sync(0xffffffffu, t.x, o);
            t.y += __shfl_xor_sync(0xffffffffu, t.y, o);
        }
        if (lane == 0) wred[0] = t;
    }
    __syncthreads();
    float2 tot = wred[0];
    float m   = tot.x * (1.0f / (float)cH);
    float var = tot.y * (1.0f / (float)cH) - m * m;
    float r = rsqrtf(fmaxf(var, 0.0f) + 1e-12f);

    float o0 = (v0 - m) * r * s[tid]       + bp[tid];
    float o1 = (v1 - m) * r * s[tid + 256] + bp[tid + 256];
    float o2 = (v2 - m) * r * s[tid + 512] + bp[tid + 512];
    orow[tid] = o0; orow[tid + 256] = o1; orow[tid + 512] = o2;
    hrow[tid]       = __float2bfloat16(o0);
    hrow[tid + 256] = __float2bfloat16(o1);
    hrow[tid + 512] = __float2bfloat16(o2);
}

__global__ __launch_bounds__(256)
void ln_k(const float* __restrict__ in, const float* __restrict__ s,
          const float* __restrict__ bp, float* __restrict__ outf,
          bf16* __restrict__ outh)
{
    const float* xr = in + (size_t)blockIdx.x * cH;
    const int tid = threadIdx.x;
    ln_core(xr[tid], xr[tid + 256], xr[tid + 512], s, bp,
            outf + (size_t)blockIdx.x * cH, outh + (size_t)blockIdx.x * cH, tid);
}

// Fused embedding + LN
__global__ __launch_bounds__(256)
void embed_ln_k(const int* __restrict__ ids, const float* __restrict__ te,
                const float* __restrict__ pe, const float* __restrict__ s,
                const float* __restrict__ bp, float* __restrict__ outf,
                bf16* __restrict__ outh)
{
    const int bs = blockIdx.x;
    const int sp = bs % cS;
    const int id = ids[bs];
    const int tid = threadIdx.x;
    const float* t0 = te + (size_t)id * cH;
    const float* p0 = pe + (size_t)sp * cH;
    float v0 = t0[tid]       + p0[tid];
    float v1 = t0[tid + 256] + p0[tid + 256];
    float v2 = t0[tid + 512] + p0[tid + 512];
    ln_core(v0, v1, v2, s, bp,
            outf + (size_t)bs * cH, outh + (size_t)bs * cH, tid);
}

// ---------------------------------------------------------------------------
// Classifier (N=19), fp32
// ---------------------------------------------------------------------------
__global__ __launch_bounds__(128)
void cls_k(const float* __restrict__ x, const float* __restrict__ W,
           const float* __restrict__ bias, float* __restrict__ logits)
{
    __shared__ float xs[cH];
    const int row = blockIdx.x;
    const int tid = threadIdx.x;
    for (int h = tid; h < cH; h += 128) xs[h] = x[(size_t)row * cH + h];
    __syncthreads();

    const int warp = tid >> 5, lane = tid & 31;
    for (int j = warp; j < cNL; j += 4) {
        float sum = 0.0f;
        for (int k2 = lane; k2 < cH; k2 += 32)
            sum = fmaf(xs[k2], W[k2 * cNL + j], sum);
        #pragma unroll
        for (int o = 16; o > 0; o >>= 1)
            sum += __shfl_down_sync(0xffffffffu, sum, o);
        if (lane == 0) logits[(size_t)row * cNL + j] = sum + bias[j];
    }
}

// ---------------------------------------------------------------------------
// CRF: numerator (warp-parallel) + forward scan (fast exp/log, prefetch).
// grid = B, 32 threads (one warp).
// ---------------------------------------------------------------------------
__global__ __launch_bounds__(32)
void crf_k(const float* __restrict__ logits, const int* __restrict__ labels,
           const int* __restrict__ amask, const float* __restrict__ startT,
           const float* __restrict__ endT, const float* __restrict__ trans,
           float* __restrict__ pb)
{
    const int b = blockIdx.x;
    const int lane = threadIdx.x;

    const int* lab = labels + b * cS;
    const int* mk  = amask + b * cS;
    const float* lg = logits + (size_t)b * cS * cNL;

    // Transition row for this lane's target tag, in registers.
    float tTrow[cNL];
    if (lane < cNL) {
        #pragma unroll
        for (int i = 0; i < cNL; i++) tTrow[i] = trans[i * cNL + lane];
    }

    // Numerator: warp-parallel over t.
    float num = 0.0f, msum = 0.0f;
    for (int t = lane; t < cS; t += 32) {
        float mf = (float)mk[t];
        msum += mf;
        if (t > 0)
            num += (trans[lab[t - 1] * cNL + lab[t]] + lg[t * cNL + lab[t]]) * mf;
    }
    #pragma unroll
    for (int o = 16; o > 0; o >>= 1) {
        num  += __shfl_xor_sync(0xffffffffu, num, o);
        msum += __shfl_xor_sync(0xffffffffu, msum, o);
    }
    int last = (int)msum - 1;
    if (lane == 0)
        num += startT[lab[0]] + lg[lab[0]] + endT[lab[last]];
    num = __shfl_sync(0xffffffffu, num, 0);

    // Forward scan
    __shared__ float al[cNL];
    if (lane < cNL) al[lane] = startT[lane] + lg[lane];
    __syncwarp();

    float lgv = (lane < cNL) ? lg[cNL + lane] : 0.0f;
    int mkv = mk[1];

    for (int t = 1; t < cS; t++) {
        float lgn = 0.0f; int mkn = 0;
        if (t + 1 < cS) {
            if (lane < cNL) lgn = lg[(t + 1) * cNL + lane];
            mkn = mk[t + 1];
        }
        float nv = 0.0f;
        if (lane < cNL) {
            float m = -1e30f;
            #pragma unroll
            for (int i = 0; i < cNL; i++) m = fmaxf(m, al[i] + tTrow[i]);
            float ss = 0.0f;
            #pragma unroll
            for (int i = 0; i < cNL; i++) ss += __expf(al[i] + tTrow[i] - m);
            float nxt = m + __logf(ss) + lgv;
            nv = (mkv > 0) ? nxt : al[lane];
        }
        __syncwarp();
        if (lane < cNL) al[lane] = nv;
        __syncwarp();
        lgv = lgn; mkv = mkn;
    }

    if (lane == 0) {
        float m = -1e30f;
        #pragma unroll
        for (int jj = 0; jj < cNL; jj++) m = fmaxf(m, al[jj] + endT[jj]);
        float ss = 0.0f;
        #pragma unroll
        for (int jj = 0; jj < cNL; jj++) ss += __expf(al[jj] + endT[jj] - m);
        pb[b] = (m + __logf(ss)) - num;
    }
}

__global__ void final_k(const float* __restrict__ pb, float* __restrict__ out)
{
    float s2 = 0.0f;
    for (int b2 = 0; b2 < cB; b2++) s2 += pb[b2];
    out[0] = s2;
}

// ---------------------------------------------------------------------------
// Launch
// ---------------------------------------------------------------------------
extern "C" void kernel_launch(void* const* d_in, const int* in_sizes, int n_in,
                              void* d_out, int out_size)
{
    const int*   ids       = (const int*)d_in[0];
    const int*   amask     = (const int*)d_in[1];
    const int*   labels    = (const int*)d_in[2];
    const float* token_emb = (const float*)d_in[3];
    const float* pos_emb   = (const float*)d_in[4];
    const float* ln_emb_s  = (const float*)d_in[5];
    const float* ln_emb_b  = (const float*)d_in[6];
    const float* Wq        = (const float*)d_in[7];
    const float* bq        = (const float*)d_in[8];
    const float* Wk        = (const float*)d_in[9];
    const float* bk        = (const float*)d_in[10];
    const float* Wv        = (const float*)d_in[11];
    const float* bv        = (const float*)d_in[12];
    const float* Wo        = (const float*)d_in[13];
    const float* bo        = (const float*)d_in[14];
    const float* ln1_s     = (const float*)d_in[15];
    const float* ln1_b     = (const float*)d_in[16];
    const float* W1        = (const float*)d_in[17];
    const float* b1        = (const float*)d_in[18];
    const float* W2        = (const float*)d_in[19];
    const float* b2        = (const float*)d_in[20];
    const float* ln2_s     = (const float*)d_in[21];
    const float* ln2_b     = (const float*)d_in[22];
    const float* cls_W     = (const float*)d_in[23];
    const float* cls_b     = (const float*)d_in[24];
    const float* startT    = (const float*)d_in[25];
    const float* endT      = (const float*)d_in[26];
    const float* trans     = (const float*)d_in[27];

    float *px, *ptmp, *plogits, *ppb, *pmaskb;
    bf16 *pxh, *pqh, *pkh, *pvh, *pctxh, *pffnh;
    bf16 *pwq, *pwk, *pwv, *pwo, *pw1, *pw2;
    cudaGetSymbolAddress((void**)&px, g_x);
    cudaGetSymbolAddress((void**)&ptmp, g_tmp);
    cudaGetSymbolAddress((void**)&pxh, g_xh);
    cudaGetSymbolAddress((void**)&pqh, g_qh);
    cudaGetSymbolAddress((void**)&pkh, g_kh);
    cudaGetSymbolAddress((void**)&pvh, g_vh);
    cudaGetSymbolAddress((void**)&pctxh, g_ctxh);
    cudaGetSymbolAddress((void**)&pffnh, g_ffnh);
    cudaGetSymbolAddress((void**)&plogits, g_logits);
    cudaGetSymbolAddress((void**)&ppb, g_pb);
    cudaGetSymbolAddress((void**)&pmaskb, g_maskb);
    cudaGetSymbolAddress((void**)&pwq, g_wq_h);
    cudaGetSymbolAddress((void**)&pwk, g_wk_h);
    cudaGetSymbolAddress((void**)&pwv, g_wv_h);
    cudaGetSymbolAddress((void**)&pwo, g_wo_h);
    cudaGetSymbolAddress((void**)&pw1, g_w1_h);
    cudaGetSymbolAddress((void**)&pw2, g_w2_h);

    // Weight conversion (once per launch), vectorized x4
    const int nHH4 = cL * cH * cH / 4;
    const int nHF4 = cL * cH * cDFF / 4;
    conv_k<<<1024, 256>>>((const float4*)Wq, (uint2*)pwq, nHH4);
    conv_k<<<1024, 256>>>((const float4*)Wk, (uint2*)pwk, nHH4);
    conv_k<<<1024, 256>>>((const float4*)Wv, (uint2*)pwv, nHH4);
    conv_k<<<1024, 256>>>((const float4*)Wo, (uint2*)pwo, nHH4);
    conv_k<<<2048, 256>>>((const float4*)W1, (uint2*)pw1, nHF4);
    conv_k<<<2048, 256>>>((const float4*)W2, (uint2*)pw2, nHF4);
    maskb_k<<<16, 256>>>(amask, pmaskb);

    embed_ln_k<<<cM, 256>>>(ids, token_emb, pos_emb, ln_emb_s, ln_emb_b, px, pxh);

    const dim3 gQKV(cH / 128, cM / 128, 3);   // (6, 32, 3)
    const dim3 gHH (cH / 128, cM / 128);      // (6, 32)
    const dim3 gHF (cDFF / 128, cM / 128);    // (24, 32)
    const dim3 gFl (cS / 128, cB * cNH);      // (4, 96)

    for (int l = 0; l < cL; l++) {
        qkv_k<<<gQKV, 256>>>(pxh, pwq + (size_t)l * cH * cH, pwk + (size_t)l * cH * cH,
                             pwv + (size_t)l * cH * cH,
                             bq + l * cH, bk + l * cH, bv + l * cH,
                             pqh, pkh, pvh, cH, cH);

        flash_k<<<gFl, 256>>>(pqh, pkh, pvh, pmaskb, pctxh);

        gemm_k<2><<<gHH, 256>>>(pctxh, pwo + (size_t)l * cH * cH, bo + l * cH, px,
                                ptmp, cH, cH);
        ln_k<<<cM, 256>>>(ptmp, ln1_s + l * cH, ln1_b + l * cH, px, pxh);

        gemm_k<1><<<gHF, 256>>>(pxh, pw1 + (size_t)l * cH * cDFF, b1 + l * cDFF, nullptr,
                                pffnh, cDFF, cH);
        gemm_k<2><<<gHH, 256>>>(pffnh, pw2 + (size_t)l * cDFF * cH, b2 + l * cH, px,
                                ptmp, cH, cDFF);
        ln_k<<<cM, 256>>>(ptmp, ln2_s + l * cH, ln2_b + l * cH, px, pxh);
    }

    cls_k<<<cM, 128>>>(px, cls_W, cls_b, plogits);
    crf_k<<<cB, 32>>>(plogits, labels, amask, startT, endT, trans, ppb);
    final_k<<<1, 1>>>(ppb, (float*)d_out);
}